// round 8
// baseline (speedup 1.0000x reference)
#include <cuda_runtime.h>
#include <math.h>
#include <stdint.h>

// ---------------- problem constants ----------------
#define S_LEN 4096
#define HID   2048
#define NH    8
#define NVH   16
#define DK    128
#define DV    128
#define KEY_DIM  (NH*DK)    // 1024
#define VAL_DIM  (NVH*DV)   // 2048
#define CONV  4
#define EPS_  1e-6f
#define SCALE_ 0.08838834764831845f   // 128^-0.5

// ---------------- workspace -------------------------------------------------
static constexpr size_t SZ_QPRE = (size_t)S_LEN * KEY_DIM;
static constexpr size_t SZ_VPRE = (size_t)S_LEN * VAL_DIM;
static constexpr size_t SZ_AB   = (size_t)S_LEN * NVH;
static constexpr size_t SZ_C    = (size_t)S_LEN * NH;

static constexpr size_t OF_QPRE = 0;
static constexpr size_t OF_KPRE = OF_QPRE + SZ_QPRE;
static constexpr size_t OF_VPRE = OF_KPRE + SZ_QPRE;
static constexpr size_t OF_GATE = OF_VPRE + SZ_VPRE;
static constexpr size_t OF_QN   = OF_GATE + SZ_VPRE;
static constexpr size_t OF_KN   = OF_QN + SZ_QPRE;
static constexpr size_t OF_VN   = OF_KN + SZ_QPRE;
static constexpr size_t OF_DB   = OF_VN + SZ_VPRE;   // float2 per (t,h)
static constexpr size_t OF_CQ   = OF_DB + 2*SZ_AB;   // C[t][hk]
static constexpr size_t OF_O    = OF_CQ + SZ_C;
static constexpr size_t OF_OG   = OF_O + SZ_VPRE;
static constexpr size_t WS_TOTAL = OF_OG + SZ_VPRE;

__device__ float g_ws_gdn[WS_TOTAL];

// ---------------- cp.async helpers -----------------------------------------
__device__ __forceinline__ void cp16(void* s, const void* g) {
    asm volatile("cp.async.ca.shared.global [%0], [%1], 16;"
                 :: "r"((uint32_t)__cvta_generic_to_shared(s)), "l"(g));
}
__device__ __forceinline__ void cp8(void* s, const void* g) {
    asm volatile("cp.async.ca.shared.global [%0], [%1], 8;"
                 :: "r"((uint32_t)__cvta_generic_to_shared(s)), "l"(g));
}
__device__ __forceinline__ void cp4(void* s, const void* g) {
    asm volatile("cp.async.ca.shared.global [%0], [%1], 4;"
                 :: "r"((uint32_t)__cvta_generic_to_shared(s)), "l"(g));
}
__device__ __forceinline__ void cp_commit() {
    asm volatile("cp.async.commit_group;");
}

// ================= tf32 tensor-core GEMM core =============================
// Fragment-major smem layout: one LDS.128 per A-fragment, LDS.64 per B-fragment.
#define GBM 128
#define GBN 128
#define GBK 16

__device__ __forceinline__ uint32_t f2tf32(float x) {
    uint32_t r;
    asm("cvt.rna.tf32.f32 %0, %1;" : "=r"(r) : "f"(x));
    return r;
}

__device__ __forceinline__ void mma_tf32(float* c, const uint32_t* a, const uint32_t* b) {
    asm volatile(
        "mma.sync.aligned.m16n8k8.row.col.f32.tf32.tf32.f32 "
        "{%0,%1,%2,%3}, {%4,%5,%6,%7}, {%8,%9}, {%0,%1,%2,%3};"
        : "+f"(c[0]), "+f"(c[1]), "+f"(c[2]), "+f"(c[3])
        : "r"(a[0]), "r"(a[1]), "r"(a[2]), "r"(a[3]), "r"(b[0]), "r"(b[1]));
}

// C[m0.., n0..] = A[M,K] * B[n0..,K]^T ; C row stride ldc. K multiple of 16.
__device__ __forceinline__ void gemm_core(
    const float* __restrict__ A, const float* __restrict__ B,
    float* __restrict__ C, int n0, int ldc, int K)
{
    // fragment-major: [buf][k8][tile][lane]
    __shared__ uint4 AsF[2][2][8][32];    // A m16k8 fragments, 16 KB
    __shared__ uint2 BsF[2][2][16][32];   // B n8k8 fragments, 16 KB

    int tid = threadIdx.x;
    int warp = tid >> 5;
    int lane = tid & 31;

    int m0 = blockIdx.y * GBM;
    int wmi = (warp >> 2) * 4;   // m16 tile base for this warp
    int wni = (warp & 3) * 4;    // n8 tile base
    int wm = wmi * 16;
    int wn = wni * 8;
    int gid = lane >> 2;
    int tig = lane & 3;

    // producer mapping: each thread handles 8 consecutive k of one row
    int lrow = tid >> 1;          // 0..127
    int k8p  = tid & 1;           // which k8 half
    int m16 = lrow >> 4;
    int rbit = (lrow >> 3) & 1;
    int pgid = lrow & 7;
    int n8 = lrow >> 3;

    const float* Ag = A + (size_t)(m0 + lrow) * K + k8p * 8;
    const float* Bg = B + (size_t)(n0 + lrow) * K + k8p * 8;

    float acc[4][4][4];
#pragma unroll
    for (int i = 0; i < 4; i++)
#pragma unroll
        for (int j = 0; j < 4; j++)
#pragma unroll
            for (int r = 0; r < 4; r++) acc[i][j][r] = 0.f;

    int kIters = K / GBK;

    float4 a0 = *(const float4*)(Ag);
    float4 a1 = *(const float4*)(Ag + 4);
    float4 b0 = *(const float4*)(Bg);
    float4 b1 = *(const float4*)(Bg + 4);

    // scatter-store one (A,B) k8 slice into fragment-major layout
    auto store_frag = [&](int buf, float4 A0, float4 A1, float4 B0, float4 B1) {
        float av[8] = {A0.x, A0.y, A0.z, A0.w, A1.x, A1.y, A1.z, A1.w};
        float bv[8] = {B0.x, B0.y, B0.z, B0.w, B1.x, B1.y, B1.z, B1.w};
        uint32_t* ab = (uint32_t*)&AsF[buf][k8p][m16][0];
        uint32_t* bb = (uint32_t*)&BsF[buf][k8p][n8][0];
#pragma unroll
        for (int j = 0; j < 8; j++) {
            int jt = j & 3, cb = j >> 2;
            ab[(pgid * 4 + jt) * 4 + rbit + 2 * cb] = f2tf32(av[j]);
            bb[(pgid * 4 + jt) * 2 + cb] = f2tf32(bv[j]);
        }
    };

    store_frag(0, a0, a1, b0, b1);
    __syncthreads();

    int buf = 0;
    for (int it = 0; it < kIters; it++) {
        bool more = (it + 1) < kIters;
        if (more) {
            const float* Agn = Ag + (size_t)(it + 1) * GBK;
            const float* Bgn = Bg + (size_t)(it + 1) * GBK;
            a0 = *(const float4*)(Agn);
            a1 = *(const float4*)(Agn + 4);
            b0 = *(const float4*)(Bgn);
            b1 = *(const float4*)(Bgn + 4);
        }

#pragma unroll
        for (int s = 0; s < 2; s++) {
            uint4 af4[4];
            uint2 bf2[4];
#pragma unroll
            for (int mt = 0; mt < 4; mt++) af4[mt] = AsF[buf][s][wmi + mt][lane];
#pragma unroll
            for (int nt = 0; nt < 4; nt++) bf2[nt] = BsF[buf][s][wni + nt][lane];
#pragma unroll
            for (int mt = 0; mt < 4; mt++)
#pragma unroll
                for (int nt = 0; nt < 4; nt++)
                    mma_tf32(acc[mt][nt], (const uint32_t*)&af4[mt],
                             (const uint32_t*)&bf2[nt]);
        }

        if (more) store_frag(buf ^ 1, a0, a1, b0, b1);
        __syncthreads();
        buf ^= 1;
    }

#pragma unroll
    for (int mt = 0; mt < 4; mt++) {
#pragma unroll
        for (int nt = 0; nt < 4; nt++) {
            int m = m0 + wm + mt * 16 + gid;
            int n = n0 + wn + nt * 8 + tig * 2;
            *(float2*)&C[(size_t)m * ldc + n] = make_float2(acc[mt][nt][0], acc[mt][nt][1]);
            *(float2*)&C[(size_t)(m + 8) * ldc + n] = make_float2(acc[mt][nt][2], acc[mt][nt][3]);
        }
    }
}

// merged x-projection: blockIdx.x 0..7 Wq, 8..15 Wk, 16..31 Wv, 32..47 Wg
__global__ __launch_bounds__(256) void gemm_x4(
    const float* __restrict__ x,
    const float* __restrict__ Wq, const float* __restrict__ Wk,
    const float* __restrict__ Wv, const float* __restrict__ Wg,
    float* __restrict__ qpre, float* __restrict__ kpre,
    float* __restrict__ vpre, float* __restrict__ gate)
{
    int bx = blockIdx.x;
    const float* B; float* C; int n0; int ldc;
    if (bx < 8)       { B = Wq; C = qpre; n0 = bx * 128;        ldc = KEY_DIM; }
    else if (bx < 16) { B = Wk; C = kpre; n0 = (bx - 8) * 128;  ldc = KEY_DIM; }
    else if (bx < 32) { B = Wv; C = vpre; n0 = (bx - 16) * 128; ldc = VAL_DIM; }
    else              { B = Wg; C = gate; n0 = (bx - 32) * 128; ldc = VAL_DIM; }
    gemm_core(x, B, C, n0, ldc, HID);
}

__global__ __launch_bounds__(256) void gemm_tf32(
    const float* __restrict__ A, const float* __restrict__ B,
    float* __restrict__ C, int N, int K)
{
    gemm_core(A, B, C, blockIdx.x * GBN, N, K);
}

// ---------------- fused a/b projection + decay/beta -----------------------
__global__ __launch_bounds__(128) void gemv_ab(
    const float* __restrict__ x, const float* __restrict__ Wa,
    const float* __restrict__ Wb, const float* __restrict__ A_log,
    const float* __restrict__ dt_bias, float2* __restrict__ db)
{
    __shared__ float xs[8][260];
    __shared__ float was[16][260];
    __shared__ float wbs[16][260];

    int tid = threadIdx.x;
    int row = tid >> 4, n = tid & 15;
    int r0 = blockIdx.x * 8;

    float acc_a = 0.f, acc_b = 0.f;
    for (int kc = 0; kc < HID; kc += 256) {
        __syncthreads();
        int lr = tid >> 4, lo = (tid & 15) * 16;
#pragma unroll
        for (int j = 0; j < 16; j += 4)
            *(float4*)&xs[lr][lo + j] = *(const float4*)&x[(size_t)(r0 + lr) * HID + kc + lo + j];
        int wr = tid >> 3, wo = (tid & 7) * 32;
#pragma unroll
        for (int j = 0; j < 32; j += 4) {
            *(float4*)&was[wr][wo + j] = *(const float4*)&Wa[(size_t)wr * HID + kc + wo + j];
            *(float4*)&wbs[wr][wo + j] = *(const float4*)&Wb[(size_t)wr * HID + kc + wo + j];
        }
        __syncthreads();
#pragma unroll 8
        for (int j = 0; j < 256; j += 4) {
            float4 xv = *(float4*)&xs[row][j];
            float4 wa = *(float4*)&was[n][j];
            float4 wb = *(float4*)&wbs[n][j];
            acc_a += xv.x*wa.x + xv.y*wa.y + xv.z*wa.z + xv.w*wa.w;
            acc_b += xv.x*wb.x + xv.y*wb.y + xv.z*wb.z + xv.w*wb.w;
        }
    }
    float a = acc_a + dt_bias[n];
    float sp = (a > 20.f) ? a : log1pf(expf(a));
    float decay = expf(-expf(A_log[n]) * sp);
    float beta = 1.f / (1.f + expf(-acc_b));
    db[(size_t)(r0 + row) * NVH + n] = make_float2(decay, beta);
}

// ---------------- conv + silu + l2norm for q/k ----------------------------
__global__ __launch_bounds__(128) void convqk_kernel(
    const float* __restrict__ pre, const float* __restrict__ cw,
    float* __restrict__ out, float scale)
{
    int t = blockIdx.x >> 3;
    int h = blockIdx.x & 7;
    int c = threadIdx.x;
    int ch = h * DK + c;
    float y = 0.f;
#pragma unroll
    for (int j = 0; j < CONV; j++) {
        int tt = t - (CONV-1) + j;
        float xv = (tt >= 0) ? pre[(size_t)tt * KEY_DIM + ch] : 0.f;
        y = fmaf(xv, cw[ch*CONV + j], y);
    }
    y = y / (1.f + expf(-y));
    float ss = y * y;
#pragma unroll
    for (int off = 16; off; off >>= 1) ss += __shfl_xor_sync(0xffffffffu, ss, off);
    __shared__ float wss[4];
    if ((threadIdx.x & 31) == 0) wss[threadIdx.x >> 5] = ss;
    __syncthreads();
    float tot = wss[0] + wss[1] + wss[2] + wss[3];
    out[(size_t)t * KEY_DIM + ch] = y * rsqrtf(tot + EPS_) * scale;
}

// ---------------- conv + silu for v ---------------------------------------
__global__ __launch_bounds__(256) void convv_kernel(
    const float* __restrict__ pre, const float* __restrict__ cw,
    float* __restrict__ out)
{
    int idx = blockIdx.x * blockDim.x + threadIdx.x;
    int t = idx >> 11;
    int ch = idx & 2047;
    float y = 0.f;
#pragma unroll
    for (int j = 0; j < CONV; j++) {
        int tt = t - (CONV-1) + j;
        float xv = (tt >= 0) ? pre[(size_t)tt * VAL_DIM + ch] : 0.f;
        y = fmaf(xv, cw[ch*CONV + j], y);
    }
    out[idx] = y / (1.f + expf(-y));
}

// ---------------- C[t][hk] = k_{t+1} . k_t per key head --------------------
__global__ __launch_bounds__(256) void dotck_kernel(
    const float* __restrict__ k, float* __restrict__ Cq)
{
    int warp = threadIdx.x >> 5;
    int lane = threadIdx.x & 31;
    int idx = blockIdx.x * 8 + warp;       // t*NH + hk
    int t = idx >> 3, hk = idx & 7;
    float cv = 0.f;
    if (t + 1 < S_LEN) {
        const float* k0 = k + (size_t)t * KEY_DIM + hk * DK + lane * 4;
        const float* k1 = k0 + KEY_DIM;
        float4 a = *(const float4*)k0;
        float4 b = *(const float4*)k1;
        cv = a.x*b.x + a.y*b.y + a.z*b.z + a.w*b.w;
#pragma unroll
        for (int off = 16; off; off >>= 1) cv += __shfl_xor_sync(0xffffffffu, cv, off);
    }
    if (lane == 0) Cq[(size_t)t * NH + hk] = cv;
}

// ---------------- delta-rule scan v3 (scalarized serial chain) -------------
#define CH 16

__global__ __launch_bounds__(128) void scan_kernel(
    const float* __restrict__ k, const float* __restrict__ q,
    const float* __restrict__ v, const float2* __restrict__ db,
    const float* __restrict__ Cq, float* __restrict__ o)
{
    __shared__ float ks[2][CH + 1][DK];
    __shared__ float qs[2][CH][DK];
    __shared__ float vs[2][CH][16];
    __shared__ float2 dbs[2][CH];
    __shared__ float cs[2][CH];

    int h = blockIdx.x >> 3;
    int hk = h >> 1;
    int colbase = (blockIdx.x & 7) * 16;
    int tid = threadIdx.x;
    int w = tid >> 5, lane = tid & 31;
    int g = lane >> 3, s = lane & 7;
    int col = colbase + w * 4 + g;

    int lr = tid >> 3;
    int lo = (tid & 7) * 16;
    int vr = tid >> 2;

    const float* kbase = k + hk * DK;
    const float* qbase = q + hk * DK;
    const float* vbase = v + h * DV + colbase + (tid & 3) * 4;
    const float2* dbase = db + h;
    const float* cbase = Cq + hk;
    float* obase = o + h * DV + col;

    {
#pragma unroll
        for (int j = 0; j < 4; j++) {
            cp16(&ks[0][lr][lo + j*4], kbase + (size_t)lr * KEY_DIM + lo + j*4);
            cp16(&qs[0][lr][lo + j*4], qbase + (size_t)lr * KEY_DIM + lo + j*4);
        }
        if (tid < 8) {
#pragma unroll
            for (int j = 0; j < 4; j++)
                cp16(&ks[0][CH][tid*16 + j*4], kbase + (size_t)CH * KEY_DIM + tid*16 + j*4);
        }
        if (tid < 64) cp16(&vs[0][vr][(tid & 3) * 4], vbase + (size_t)vr * VAL_DIM);
        if (tid < CH) cp8(&dbs[0][tid], dbase + (size_t)tid * NVH);
        if (tid < CH) cp4(&cs[0][tid], cbase + (size_t)tid * NH);
        cp_commit();
    }

    float S[16];
#pragma unroll
    for (int i = 0; i < 16; i++) S[i] = 0.f;
    float P1 = 0.f;
    float kc[16];
    bool kc_init = false;

    int buf = 0;
    const int NCH = S_LEN / CH;
    for (int c = 0; c < NCH; c++) {
        if (c + 1 < NCH) {
            int t0 = (c + 1) * CH;
            int p = buf ^ 1;
#pragma unroll
            for (int j = 0; j < 4; j++) {
                cp16(&ks[p][lr][lo + j*4], kbase + (size_t)(t0 + lr) * KEY_DIM + lo + j*4);
                cp16(&qs[p][lr][lo + j*4], qbase + (size_t)(t0 + lr) * KEY_DIM + lo + j*4);
            }
            if (tid < 8) {
                int ovr = t0 + CH; if (ovr > S_LEN - 1) ovr = S_LEN - 1;
#pragma unroll
                for (int j = 0; j < 4; j++)
                    cp16(&ks[p][CH][tid*16 + j*4], kbase + (size_t)ovr * KEY_DIM + tid*16 + j*4);
            }
            if (tid < 64) cp16(&vs[p][vr][(tid & 3) * 4], vbase + (size_t)(t0 + vr) * VAL_DIM);
            if (tid < CH) cp8(&dbs[p][tid], dbase + (size_t)(t0 + tid) * NVH);
            if (tid < CH) cp4(&cs[p][tid], cbase + (size_t)(t0 + tid) * NH);
            cp_commit();
            asm volatile("cp.async.wait_group 1;");
        } else {
            asm volatile("cp.async.wait_group 0;");
        }
        __syncthreads();

        if (!kc_init) {
#pragma unroll
            for (int i = 0; i < 16; i += 4)
                *(float4*)&kc[i] = *(const float4*)&ks[0][0][s * 16 + i];
            kc_init = true;
        }

        int t0 = c * CH;
        float* ob = obase + (size_t)t0 * VAL_DIM;
#pragma unroll
        for (int tt = 0; tt < CH; tt++) {
            float kn[16], qc[16];
#pragma unroll
            for (int i = 0; i < 16; i += 4) {
                *(float4*)&kn[i] = *(const float4*)&ks[buf][tt + 1][s * 16 + i];
                *(float4*)&qc[i] = *(const float4*)&qs[buf][tt][s * 16 + i];
            }
            float vc = vs[buf][tt][w * 4 + g];
            float2 dc = dbs[buf][tt];
            float Ct = cs[buf][tt];

            float a0 = 0.f, a1 = 0.f, a2 = 0.f, a3 = 0.f;
#pragma unroll
            for (int i = 0; i < 16; i += 4) {
                a0 = fmaf(kn[i],   S[i],   a0);
                a1 = fmaf(kn[i+1], S[i+1], a1);
                a2 = fmaf(kn[i+2], S[i+2], a2);
                a3 = fmaf(kn[i+3], S[i+3], a3);
            }
            float A = (a0 + a1) + (a2 + a3);

            float delta = (vc - dc.x * P1) * dc.y;

            float b0 = 0.f, b1 = 0.f, b2 = 0.f, b3 = 0.f;
#pragma unroll
            for (int i = 0; i < 16; i += 4) {
                S[i]   = fmaf(S[i],   dc.x, kc[i]   * delta);
                S[i+1] = fmaf(S[i+1], dc.x, kc[i+1] * delta);
                S[i+2] = fmaf(S[i+2], dc.x, kc[i+2] * delta);
                S[i+3] = fmaf(S[i+3], dc.x, kc[i+3] * delta);
                b0 = fmaf(qc[i],   S[i],   b0);
                b1 = fmaf(qc[i+1], S[i+1], b1);
                b2 = fmaf(qc[i+2], S[i+2], b2);
                b3 = fmaf(qc[i+3], S[i+3], b3);
            }
            float ov = (b0 + b1) + (b2 + b3);

            A  += __shfl_xor_sync(0xffffffffu, A, 1);
            A  += __shfl_xor_sync(0xffffffffu, A, 2);
            A  += __shfl_xor_sync(0xffffffffu, A, 4);
            ov += __shfl_xor_sync(0xffffffffu, ov, 1);
            ov += __shfl_xor_sync(0xffffffffu, ov, 2);
            ov += __shfl_xor_sync(0xffffffffu, ov, 4);
            if (s == 0) ob[(size_t)tt * VAL_DIM] = ov;

            P1 = fmaf(dc.x, A, Ct * delta);
#pragma unroll
            for (int i = 0; i < 16; i++) kc[i] = kn[i];
        }
        __syncthreads();
        buf ^= 1;
    }
}

// ---------------- gated RMS norm ------------------------------------------
__global__ __launch_bounds__(128) void gnorm_kernel(
    const float* __restrict__ o, const float* __restrict__ gate,
    const float* __restrict__ w_norm, float* __restrict__ og)
{
    int t = blockIdx.x >> 4;
    int h = blockIdx.x & 15;
    int c = threadIdx.x;
    size_t idx = (size_t)t * VAL_DIM + h * DV + c;
    float gt = gate[idx];
    float y = o[idx] * (gt / (1.f + expf(-gt)));
    float ss = y * y;
#pragma unroll
    for (int off = 16; off; off >>= 1) ss += __shfl_xor_sync(0xffffffffu, ss, off);
    __shared__ float wss[4];
    if ((threadIdx.x & 31) == 0) wss[threadIdx.x >> 5] = ss;
    __syncthreads();
    float mean = (wss[0] + wss[1] + wss[2] + wss[3]) * (1.f / DV);
    og[idx] = y * rsqrtf(mean + EPS_) * w_norm[c];
}

// ---------------- launch ---------------------------------------------------
extern "C" void kernel_launch(void* const* d_in, const int* in_sizes, int n_in,
                              void* d_out, int out_size)
{
    const float* x      = (const float*)d_in[0];
    const float* Wq     = (const float*)d_in[1];
    const float* Wk     = (const float*)d_in[2];
    const float* Wv     = (const float*)d_in[3];
    const float* Wa     = (const float*)d_in[4];
    const float* Wb     = (const float*)d_in[5];
    const float* Wg     = (const float*)d_in[6];
    const float* Wo     = (const float*)d_in[7];
    const float* conv_q = (const float*)d_in[8];
    const float* conv_k = (const float*)d_in[9];
    const float* conv_v = (const float*)d_in[10];
    const float* A_log  = (const float*)d_in[11];
    const float* dt_b   = (const float*)d_in[12];
    const float* w_norm = (const float*)d_in[13];

    void* wsp = nullptr;
    cudaGetSymbolAddress(&wsp, g_ws_gdn);
    float* ws = (float*)wsp;
    float* qpre = ws + OF_QPRE;
    float* kpre = ws + OF_KPRE;
    float* vpre = ws + OF_VPRE;
    float* gate = ws + OF_GATE;
    float* qn   = ws + OF_QN;
    float* kn   = ws + OF_KN;
    float* vn   = ws + OF_VN;
    float2* db  = (float2*)(ws + OF_DB);
    float* Cq   = ws + OF_CQ;
    float* o    = ws + OF_O;
    float* og   = ws + OF_OG;
    float* out  = (float*)d_out;

    dim3 blk(256);
    dim3 g_x4(48, S_LEN / GBM);              // merged Wq/Wk/Wv/Wg
    dim3 g_o (VAL_DIM / GBN, S_LEN / GBM);   // Wo: (16,32)

    gemm_x4<<<g_x4, blk>>>(x, Wq, Wk, Wv, Wg, qpre, kpre, vpre, gate);
    gemv_ab<<<S_LEN / 8, 128>>>(x, Wa, Wb, A_log, dt_b, db);

    convqk_kernel<<<S_LEN * NH, 128>>>(qpre, conv_q, qn, SCALE_);
    convqk_kernel<<<S_LEN * NH, 128>>>(kpre, conv_k, kn, 1.f);
    convv_kernel<<<(S_LEN * VAL_DIM) / 256, 256>>>(vpre, conv_v, vn);
    dotck_kernel<<<S_LEN * NH / 8, 256>>>(kn, Cq);

    scan_kernel<<<128, 128>>>(kn, qn, vn, db, Cq, o);

    gnorm_kernel<<<S_LEN * NVH, 128>>>(o, gate, w_norm, og);

    gemm_tf32<<<g_o, blk>>>(og, Wo, out, HID, VAL_DIM);
}

// round 9
// speedup vs baseline: 1.1180x; 1.1180x over previous
#include <cuda_runtime.h>
#include <math.h>
#include <stdint.h>

// ---------------- problem constants ----------------
#define S_LEN 4096
#define HID   2048
#define NH    8
#define NVH   16
#define DK    128
#define DV    128
#define KEY_DIM  (NH*DK)    // 1024
#define VAL_DIM  (NVH*DV)   // 2048
#define CONV  4
#define EPS_  1e-6f
#define SCALE_ 0.08838834764831845f   // 128^-0.5

// ---------------- workspace -------------------------------------------------
static constexpr size_t SZ_QPRE = (size_t)S_LEN * KEY_DIM;
static constexpr size_t SZ_VPRE = (size_t)S_LEN * VAL_DIM;
static constexpr size_t SZ_AB   = (size_t)S_LEN * NVH;
static constexpr size_t SZ_C    = (size_t)S_LEN * NH;
static constexpr size_t SZ_X    = (size_t)S_LEN * HID;
static constexpr size_t SZ_WQK  = (size_t)KEY_DIM * HID;
static constexpr size_t SZ_WV   = (size_t)VAL_DIM * HID;

static constexpr size_t OF_QPRE = 0;
static constexpr size_t OF_KPRE = OF_QPRE + SZ_QPRE;
static constexpr size_t OF_VPRE = OF_KPRE + SZ_QPRE;
static constexpr size_t OF_GATE = OF_VPRE + SZ_VPRE;
static constexpr size_t OF_QN   = OF_GATE + SZ_VPRE;
static constexpr size_t OF_KN   = OF_QN + SZ_QPRE;
static constexpr size_t OF_VN   = OF_KN + SZ_QPRE;
static constexpr size_t OF_DB   = OF_VN + SZ_VPRE;   // float2 per (t,h)
static constexpr size_t OF_CQ   = OF_DB + 2*SZ_AB;   // C[t][hk]
static constexpr size_t OF_O    = OF_CQ + SZ_C;
static constexpr size_t OF_OG   = OF_O + SZ_VPRE;
static constexpr size_t OF_XT   = OF_OG + SZ_VPRE;   // tf32 copies
static constexpr size_t OF_WQT  = OF_XT + SZ_X;
static constexpr size_t OF_WKT  = OF_WQT + SZ_WQK;
static constexpr size_t OF_WVT  = OF_WKT + SZ_WQK;
static constexpr size_t OF_WGT  = OF_WVT + SZ_WV;
static constexpr size_t OF_WOT  = OF_WGT + SZ_WV;
static constexpr size_t WS_TOTAL = OF_WOT + SZ_WV;

__device__ float g_ws_gdn[WS_TOTAL];

// ---------------- cp.async helpers -----------------------------------------
__device__ __forceinline__ void cp16(void* s, const void* g) {
    asm volatile("cp.async.ca.shared.global [%0], [%1], 16;"
                 :: "r"((uint32_t)__cvta_generic_to_shared(s)), "l"(g));
}
__device__ __forceinline__ void cp8(void* s, const void* g) {
    asm volatile("cp.async.ca.shared.global [%0], [%1], 8;"
                 :: "r"((uint32_t)__cvta_generic_to_shared(s)), "l"(g));
}
__device__ __forceinline__ void cp4(void* s, const void* g) {
    asm volatile("cp.async.ca.shared.global [%0], [%1], 4;"
                 :: "r"((uint32_t)__cvta_generic_to_shared(s)), "l"(g));
}
__device__ __forceinline__ void cp_commit() {
    asm volatile("cp.async.commit_group;");
}

// ---------------- tf32 helpers ---------------------------------------------
__device__ __forceinline__ uint32_t f2tf32(float x) {
    uint32_t r;
    asm("cvt.rna.tf32.f32 %0, %1;" : "=r"(r) : "f"(x));
    return r;
}
__device__ __forceinline__ float tf32f(float x) {
    return __uint_as_float(f2tf32(x));
}

__global__ __launch_bounds__(256) void cvt_tf32_kernel(
    const float* __restrict__ in, float* __restrict__ out, int n)
{
    int i = (blockIdx.x * 256 + threadIdx.x) * 4;
    if (i >= n) return;
    float4 v = *(const float4*)(in + i);
    float4 o = make_float4(tf32f(v.x), tf32f(v.y), tf32f(v.z), tf32f(v.w));
    *(float4*)(out + i) = o;
}

// ================= tf32 tensor-core GEMM (4-stage cp.async) ================
// A, B are ALREADY tf32-rounded fp32. C fp32. M%128==0, N%128==0, K%16==0.
#define GBM 128
#define GBN 128
#define GBK 16
#define PADW 20                         // row stride in floats (80B: 16B-aligned, conflict-free)
#define STAGE_F (2 * GBM * PADW)        // 5120 floats per stage (A then B)
#define NSTAGE 4
#define GDYN_SMEM (NSTAGE * STAGE_F * 4)  // 81920 bytes

__device__ __forceinline__ void mma_tf32(float* c, const uint32_t* a, const uint32_t* b) {
    asm volatile(
        "mma.sync.aligned.m16n8k8.row.col.f32.tf32.tf32.f32 "
        "{%0,%1,%2,%3}, {%4,%5,%6,%7}, {%8,%9}, {%0,%1,%2,%3};"
        : "+f"(c[0]), "+f"(c[1]), "+f"(c[2]), "+f"(c[3])
        : "r"(a[0]), "r"(a[1]), "r"(a[2]), "r"(a[3]), "r"(b[0]), "r"(b[1]));
}

__device__ __forceinline__ void gemm_core(
    const float* __restrict__ A, const float* __restrict__ B,
    float* __restrict__ C, int n0, int ldc, int K)
{
    extern __shared__ float smg[];

    int tid = threadIdx.x;
    int warp = tid >> 5;
    int lane = tid & 31;
    int gid = lane >> 2;
    int tig = lane & 3;

    int m0 = blockIdx.y * GBM;
    int wm = (warp >> 2) * 64;
    int wn = (warp & 3) * 32;

    int lrow = tid >> 1;
    int lk   = (tid & 1) * 8;
    const float* Ag = A + (size_t)(m0 + lrow) * K + lk;
    const float* Bg = B + (size_t)(n0 + lrow) * K + lk;
    int sA = lrow * PADW + lk;
    int sB = GBM * PADW + lrow * PADW + lk;

    float acc[4][4][4];
#pragma unroll
    for (int i = 0; i < 4; i++)
#pragma unroll
        for (int j = 0; j < 4; j++)
#pragma unroll
            for (int r = 0; r < 4; r++) acc[i][j][r] = 0.f;

    int kIters = K / GBK;

    // preload stages 0..2
#pragma unroll
    for (int s = 0; s < 3; s++) {
        float* stg = smg + s * STAGE_F;
        cp16(stg + sA,     Ag + (size_t)s * GBK);
        cp16(stg + sA + 4, Ag + (size_t)s * GBK + 4);
        cp16(stg + sB,     Bg + (size_t)s * GBK);
        cp16(stg + sB + 4, Bg + (size_t)s * GBK + 4);
        cp_commit();
    }

    for (int it = 0; it < kIters; it++) {
        asm volatile("cp.async.wait_group 2;");
        __syncthreads();

        // issue stage it+3 (slot reused from iter it-1; safe after the sync)
        if (it + 3 < kIters) {
            float* stg = smg + ((it + 3) & 3) * STAGE_F;
            cp16(stg + sA,     Ag + (size_t)(it + 3) * GBK);
            cp16(stg + sA + 4, Ag + (size_t)(it + 3) * GBK + 4);
            cp16(stg + sB,     Bg + (size_t)(it + 3) * GBK);
            cp16(stg + sB + 4, Bg + (size_t)(it + 3) * GBK + 4);
        }
        cp_commit();

        const float* Sa = smg + (it & 3) * STAGE_F;
        const float* Sb = Sa + GBM * PADW;

#pragma unroll
        for (int s = 0; s < 2; s++) {
            int k8 = s * 8;
            uint32_t af[4][4], bf[4][2];
#pragma unroll
            for (int mt = 0; mt < 4; mt++) {
                int r = wm + mt * 16 + gid;
                af[mt][0] = __float_as_uint(Sa[r * PADW + k8 + tig]);
                af[mt][1] = __float_as_uint(Sa[(r + 8) * PADW + k8 + tig]);
                af[mt][2] = __float_as_uint(Sa[r * PADW + k8 + tig + 4]);
                af[mt][3] = __float_as_uint(Sa[(r + 8) * PADW + k8 + tig + 4]);
            }
#pragma unroll
            for (int nt = 0; nt < 4; nt++) {
                int c = wn + nt * 8 + gid;
                bf[nt][0] = __float_as_uint(Sb[c * PADW + k8 + tig]);
                bf[nt][1] = __float_as_uint(Sb[c * PADW + k8 + tig + 4]);
            }
#pragma unroll
            for (int mt = 0; mt < 4; mt++)
#pragma unroll
                for (int nt = 0; nt < 4; nt++)
                    mma_tf32(acc[mt][nt], af[mt], bf[nt]);
        }
    }

#pragma unroll
    for (int mt = 0; mt < 4; mt++) {
#pragma unroll
        for (int nt = 0; nt < 4; nt++) {
            int m = m0 + wm + mt * 16 + gid;
            int n = n0 + wn + nt * 8 + tig * 2;
            *(float2*)&C[(size_t)m * ldc + n] = make_float2(acc[mt][nt][0], acc[mt][nt][1]);
            *(float2*)&C[(size_t)(m + 8) * ldc + n] = make_float2(acc[mt][nt][2], acc[mt][nt][3]);
        }
    }
}

// merged x-projection: blockIdx.x 0..7 Wq, 8..15 Wk, 16..31 Wv, 32..47 Wg
__global__ __launch_bounds__(256, 2) void gemm_x4(
    const float* __restrict__ x,
    const float* __restrict__ Wq, const float* __restrict__ Wk,
    const float* __restrict__ Wv, const float* __restrict__ Wg,
    float* __restrict__ qpre, float* __restrict__ kpre,
    float* __restrict__ vpre, float* __restrict__ gate)
{
    int bx = blockIdx.x;
    const float* B; float* C; int n0; int ldc;
    if (bx < 8)       { B = Wq; C = qpre; n0 = bx * 128;        ldc = KEY_DIM; }
    else if (bx < 16) { B = Wk; C = kpre; n0 = (bx - 8) * 128;  ldc = KEY_DIM; }
    else if (bx < 32) { B = Wv; C = vpre; n0 = (bx - 16) * 128; ldc = VAL_DIM; }
    else              { B = Wg; C = gate; n0 = (bx - 32) * 128; ldc = VAL_DIM; }
    gemm_core(x, B, C, n0, ldc, HID);
}

__global__ __launch_bounds__(256, 2) void gemm_tf32(
    const float* __restrict__ A, const float* __restrict__ B,
    float* __restrict__ C, int N, int K)
{
    gemm_core(A, B, C, blockIdx.x * GBN, N, K);
}

// ---------------- fused a/b projection + decay/beta -----------------------
__global__ __launch_bounds__(128) void gemv_ab(
    const float* __restrict__ x, const float* __restrict__ Wa,
    const float* __restrict__ Wb, const float* __restrict__ A_log,
    const float* __restrict__ dt_bias, float2* __restrict__ db)
{
    __shared__ float xs[8][260];
    __shared__ float was[16][260];
    __shared__ float wbs[16][260];

    int tid = threadIdx.x;
    int row = tid >> 4, n = tid & 15;
    int r0 = blockIdx.x * 8;

    float acc_a = 0.f, acc_b = 0.f;
    for (int kc = 0; kc < HID; kc += 256) {
        __syncthreads();
        int lr = tid >> 4, lo = (tid & 15) * 16;
#pragma unroll
        for (int j = 0; j < 16; j += 4)
            *(float4*)&xs[lr][lo + j] = *(const float4*)&x[(size_t)(r0 + lr) * HID + kc + lo + j];
        int wr = tid >> 3, wo = (tid & 7) * 32;
#pragma unroll
        for (int j = 0; j < 32; j += 4) {
            *(float4*)&was[wr][wo + j] = *(const float4*)&Wa[(size_t)wr * HID + kc + wo + j];
            *(float4*)&wbs[wr][wo + j] = *(const float4*)&Wb[(size_t)wr * HID + kc + wo + j];
        }
        __syncthreads();
#pragma unroll 8
        for (int j = 0; j < 256; j += 4) {
            float4 xv = *(float4*)&xs[row][j];
            float4 wa = *(float4*)&was[n][j];
            float4 wb = *(float4*)&wbs[n][j];
            acc_a += xv.x*wa.x + xv.y*wa.y + xv.z*wa.z + xv.w*wa.w;
            acc_b += xv.x*wb.x + xv.y*wb.y + xv.z*wb.z + xv.w*wb.w;
        }
    }
    float a = acc_a + dt_bias[n];
    float sp = (a > 20.f) ? a : log1pf(expf(a));
    float decay = expf(-expf(A_log[n]) * sp);
    float beta = 1.f / (1.f + expf(-acc_b));
    db[(size_t)(r0 + row) * NVH + n] = make_float2(decay, beta);
}

// ---------------- conv + silu + l2norm for q/k ----------------------------
__global__ __launch_bounds__(128) void convqk_kernel(
    const float* __restrict__ pre, const float* __restrict__ cw,
    float* __restrict__ out, float scale)
{
    int t = blockIdx.x >> 3;
    int h = blockIdx.x & 7;
    int c = threadIdx.x;
    int ch = h * DK + c;
    float y = 0.f;
#pragma unroll
    for (int j = 0; j < CONV; j++) {
        int tt = t - (CONV-1) + j;
        float xv = (tt >= 0) ? pre[(size_t)tt * KEY_DIM + ch] : 0.f;
        y = fmaf(xv, cw[ch*CONV + j], y);
    }
    y = y / (1.f + expf(-y));
    float ss = y * y;
#pragma unroll
    for (int off = 16; off; off >>= 1) ss += __shfl_xor_sync(0xffffffffu, ss, off);
    __shared__ float wss[4];
    if ((threadIdx.x & 31) == 0) wss[threadIdx.x >> 5] = ss;
    __syncthreads();
    float tot = wss[0] + wss[1] + wss[2] + wss[3];
    out[(size_t)t * KEY_DIM + ch] = y * rsqrtf(tot + EPS_) * scale;
}

// ---------------- conv + silu for v ---------------------------------------
__global__ __launch_bounds__(256) void convv_kernel(
    const float* __restrict__ pre, const float* __restrict__ cw,
    float* __restrict__ out)
{
    int idx = blockIdx.x * blockDim.x + threadIdx.x;
    int t = idx >> 11;
    int ch = idx & 2047;
    float y = 0.f;
#pragma unroll
    for (int j = 0; j < CONV; j++) {
        int tt = t - (CONV-1) + j;
        float xv = (tt >= 0) ? pre[(size_t)tt * VAL_DIM + ch] : 0.f;
        y = fmaf(xv, cw[ch*CONV + j], y);
    }
    out[idx] = y / (1.f + expf(-y));
}

// ---------------- C[t][hk] = k_{t+1} . k_t per key head --------------------
__global__ __launch_bounds__(256) void dotck_kernel(
    const float* __restrict__ k, float* __restrict__ Cq)
{
    int warp = threadIdx.x >> 5;
    int lane = threadIdx.x & 31;
    int idx = blockIdx.x * 8 + warp;       // t*NH + hk
    int t = idx >> 3, hk = idx & 7;
    float cv = 0.f;
    if (t + 1 < S_LEN) {
        const float* k0 = k + (size_t)t * KEY_DIM + hk * DK + lane * 4;
        const float* k1 = k0 + KEY_DIM;
        float4 a = *(const float4*)k0;
        float4 b = *(const float4*)k1;
        cv = a.x*b.x + a.y*b.y + a.z*b.z + a.w*b.w;
#pragma unroll
        for (int off = 16; off; off >>= 1) cv += __shfl_xor_sync(0xffffffffu, cv, off);
    }
    if (lane == 0) Cq[(size_t)t * NH + hk] = cv;
}

// ---------------- delta-rule scan v3 (scalarized serial chain) -------------
#define CH 16

__global__ __launch_bounds__(128) void scan_kernel(
    const float* __restrict__ k, const float* __restrict__ q,
    const float* __restrict__ v, const float2* __restrict__ db,
    const float* __restrict__ Cq, float* __restrict__ o)
{
    __shared__ float ks[2][CH + 1][DK];
    __shared__ float qs[2][CH][DK];
    __shared__ float vs[2][CH][16];
    __shared__ float2 dbs[2][CH];
    __shared__ float cs[2][CH];

    int h = blockIdx.x >> 3;
    int hk = h >> 1;
    int colbase = (blockIdx.x & 7) * 16;
    int tid = threadIdx.x;
    int w = tid >> 5, lane = tid & 31;
    int g = lane >> 3, s = lane & 7;
    int col = colbase + w * 4 + g;

    int lr = tid >> 3;
    int lo = (tid & 7) * 16;
    int vr = tid >> 2;

    const float* kbase = k + hk * DK;
    const float* qbase = q + hk * DK;
    const float* vbase = v + h * DV + colbase + (tid & 3) * 4;
    const float2* dbase = db + h;
    const float* cbase = Cq + hk;
    float* obase = o + h * DV + col;

    {
#pragma unroll
        for (int j = 0; j < 4; j++) {
            cp16(&ks[0][lr][lo + j*4], kbase + (size_t)lr * KEY_DIM + lo + j*4);
            cp16(&qs[0][lr][lo + j*4], qbase + (size_t)lr * KEY_DIM + lo + j*4);
        }
        if (tid < 8) {
#pragma unroll
            for (int j = 0; j < 4; j++)
                cp16(&ks[0][CH][tid*16 + j*4], kbase + (size_t)CH * KEY_DIM + tid*16 + j*4);
        }
        if (tid < 64) cp16(&vs[0][vr][(tid & 3) * 4], vbase + (size_t)vr * VAL_DIM);
        if (tid < CH) cp8(&dbs[0][tid], dbase + (size_t)tid * NVH);
        if (tid < CH) cp4(&cs[0][tid], cbase + (size_t)tid * NH);
        cp_commit();
    }

    float S[16];
#pragma unroll
    for (int i = 0; i < 16; i++) S[i] = 0.f;
    float P1 = 0.f;
    float kc[16];
    bool kc_init = false;

    int buf = 0;
    const int NCH = S_LEN / CH;
    for (int c = 0; c < NCH; c++) {
        if (c + 1 < NCH) {
            int t0 = (c + 1) * CH;
            int p = buf ^ 1;
#pragma unroll
            for (int j = 0; j < 4; j++) {
                cp16(&ks[p][lr][lo + j*4], kbase + (size_t)(t0 + lr) * KEY_DIM + lo + j*4);
                cp16(&qs[p][lr][lo + j*4], qbase + (size_t)(t0 + lr) * KEY_DIM + lo + j*4);
            }
            if (tid < 8) {
                int ovr = t0 + CH; if (ovr > S_LEN - 1) ovr = S_LEN - 1;
#pragma unroll
                for (int j = 0; j < 4; j++)
                    cp16(&ks[p][CH][tid*16 + j*4], kbase + (size_t)ovr * KEY_DIM + tid*16 + j*4);
            }
            if (tid < 64) cp16(&vs[p][vr][(tid & 3) * 4], vbase + (size_t)(t0 + vr) * VAL_DIM);
            if (tid < CH) cp8(&dbs[p][tid], dbase + (size_t)(t0 + tid) * NVH);
            if (tid < CH) cp4(&cs[p][tid], cbase + (size_t)(t0 + tid) * NH);
            cp_commit();
            asm volatile("cp.async.wait_group 1;");
        } else {
            asm volatile("cp.async.wait_group 0;");
        }
        __syncthreads();

        if (!kc_init) {
#pragma unroll
            for (int i = 0; i < 16; i += 4)
                *(float4*)&kc[i] = *(const float4*)&ks[0][0][s * 16 + i];
            kc_init = true;
        }

        int t0 = c * CH;
        float* ob = obase + (size_t)t0 * VAL_DIM;
#pragma unroll
        for (int tt = 0; tt < CH; tt++) {
            float kn[16], qc[16];
#pragma unroll
            for (int i = 0; i < 16; i += 4) {
                *(float4*)&kn[i] = *(const float4*)&ks[buf][tt + 1][s * 16 + i];
                *(float4*)&qc[i] = *(const float4*)&qs[buf][tt][s * 16 + i];
            }
            float vc = vs[buf][tt][w * 4 + g];
            float2 dc = dbs[buf][tt];
            float Ct = cs[buf][tt];

            float a0 = 0.f, a1 = 0.f, a2 = 0.f, a3 = 0.f;
#pragma unroll
            for (int i = 0; i < 16; i += 4) {
                a0 = fmaf(kn[i],   S[i],   a0);
                a1 = fmaf(kn[i+1], S[i+1], a1);
                a2 = fmaf(kn[i+2], S[i+2], a2);
                a3 = fmaf(kn[i+3], S[i+3], a3);
            }
            float A = (a0 + a1) + (a2 + a3);

            float delta = (vc - dc.x * P1) * dc.y;

            float b0 = 0.f, b1 = 0.f, b2 = 0.f, b3 = 0.f;
#pragma unroll
            for (int i = 0; i < 16; i += 4) {
                S[i]   = fmaf(S[i],   dc.x, kc[i]   * delta);
                S[i+1] = fmaf(S[i+1], dc.x, kc[i+1] * delta);
                S[i+2] = fmaf(S[i+2], dc.x, kc[i+2] * delta);
                S[i+3] = fmaf(S[i+3], dc.x, kc[i+3] * delta);
                b0 = fmaf(qc[i],   S[i],   b0);
                b1 = fmaf(qc[i+1], S[i+1], b1);
                b2 = fmaf(qc[i+2], S[i+2], b2);
                b3 = fmaf(qc[i+3], S[i+3], b3);
            }
            float ov = (b0 + b1) + (b2 + b3);

            A  += __shfl_xor_sync(0xffffffffu, A, 1);
            A  += __shfl_xor_sync(0xffffffffu, A, 2);
            A  += __shfl_xor_sync(0xffffffffu, A, 4);
            ov += __shfl_xor_sync(0xffffffffu, ov, 1);
            ov += __shfl_xor_sync(0xffffffffu, ov, 2);
            ov += __shfl_xor_sync(0xffffffffu, ov, 4);
            if (s == 0) ob[(size_t)tt * VAL_DIM] = ov;

            P1 = fmaf(dc.x, A, Ct * delta);
#pragma unroll
            for (int i = 0; i < 16; i++) kc[i] = kn[i];
        }
        __syncthreads();
        buf ^= 1;
    }
}

// ---------------- gated RMS norm (emits tf32-rounded og) -------------------
__global__ __launch_bounds__(128) void gnorm_kernel(
    const float* __restrict__ o, const float* __restrict__ gate,
    const float* __restrict__ w_norm, float* __restrict__ og)
{
    int t = blockIdx.x >> 4;
    int h = blockIdx.x & 15;
    int c = threadIdx.x;
    size_t idx = (size_t)t * VAL_DIM + h * DV + c;
    float gt = gate[idx];
    float y = o[idx] * (gt / (1.f + expf(-gt)));
    float ss = y * y;
#pragma unroll
    for (int off = 16; off; off >>= 1) ss += __shfl_xor_sync(0xffffffffu, ss, off);
    __shared__ float wss[4];
    if ((threadIdx.x & 31) == 0) wss[threadIdx.x >> 5] = ss;
    __syncthreads();
    float mean = (wss[0] + wss[1] + wss[2] + wss[3]) * (1.f / DV);
    og[idx] = tf32f(y * rsqrtf(mean + EPS_) * w_norm[c]);
}

// ---------------- launch ---------------------------------------------------
extern "C" void kernel_launch(void* const* d_in, const int* in_sizes, int n_in,
                              void* d_out, int out_size)
{
    const float* x      = (const float*)d_in[0];
    const float* Wq     = (const float*)d_in[1];
    const float* Wk     = (const float*)d_in[2];
    const float* Wv     = (const float*)d_in[3];
    const float* Wa     = (const float*)d_in[4];
    const float* Wb     = (const float*)d_in[5];
    const float* Wg     = (const float*)d_in[6];
    const float* Wo     = (const float*)d_in[7];
    const float* conv_q = (const float*)d_in[8];
    const float* conv_k = (const float*)d_in[9];
    const float* conv_v = (const float*)d_in[10];
    const float* A_log  = (const float*)d_in[11];
    const float* dt_b   = (const float*)d_in[12];
    const float* w_norm = (const float*)d_in[13];

    void* wsp = nullptr;
    cudaGetSymbolAddress(&wsp, g_ws_gdn);
    float* ws = (float*)wsp;
    float* qpre = ws + OF_QPRE;
    float* kpre = ws + OF_KPRE;
    float* vpre = ws + OF_VPRE;
    float* gate = ws + OF_GATE;
    float* qn   = ws + OF_QN;
    float* kn   = ws + OF_KN;
    float* vn   = ws + OF_VN;
    float2* db  = (float2*)(ws + OF_DB);
    float* Cq   = ws + OF_CQ;
    float* o    = ws + OF_O;
    float* og   = ws + OF_OG;
    float* xt   = ws + OF_XT;
    float* wqt  = ws + OF_WQT;
    float* wkt  = ws + OF_WKT;
    float* wvt  = ws + OF_WVT;
    float* wgt  = ws + OF_WGT;
    float* wot  = ws + OF_WOT;
    float* out  = (float*)d_out;

    cudaFuncSetAttribute(gemm_x4, cudaFuncAttributeMaxDynamicSharedMemorySize, GDYN_SMEM);
    cudaFuncSetAttribute(gemm_tf32, cudaFuncAttributeMaxDynamicSharedMemorySize, GDYN_SMEM);

    // tf32 pre-conversion (bandwidth-bound, ~30us total)
    cvt_tf32_kernel<<<(int)(SZ_X   / 1024), 256>>>(x,  xt,  (int)SZ_X);
    cvt_tf32_kernel<<<(int)(SZ_WQK / 1024), 256>>>(Wq, wqt, (int)SZ_WQK);
    cvt_tf32_kernel<<<(int)(SZ_WQK / 1024), 256>>>(Wk, wkt, (int)SZ_WQK);
    cvt_tf32_kernel<<<(int)(SZ_WV  / 1024), 256>>>(Wv, wvt, (int)SZ_WV);
    cvt_tf32_kernel<<<(int)(SZ_WV  / 1024), 256>>>(Wg, wgt, (int)SZ_WV);
    cvt_tf32_kernel<<<(int)(SZ_WV  / 1024), 256>>>(Wo, wot, (int)SZ_WV);

    dim3 blk(256);
    dim3 g_x4(48, S_LEN / GBM);              // merged Wq/Wk/Wv/Wg
    dim3 g_o (VAL_DIM / GBN, S_LEN / GBM);   // Wo: (16,32)

    gemm_x4<<<g_x4, blk, GDYN_SMEM>>>(xt, wqt, wkt, wvt, wgt, qpre, kpre, vpre, gate);
    gemv_ab<<<S_LEN / 8, 128>>>(x, Wa, Wb, A_log, dt_b, db);

    convqk_kernel<<<S_LEN * NH, 128>>>(qpre, conv_q, qn, SCALE_);
    convqk_kernel<<<S_LEN * NH, 128>>>(kpre, conv_k, kn, 1.f);
    convv_kernel<<<(S_LEN * VAL_DIM) / 256, 256>>>(vpre, conv_v, vn);
    dotck_kernel<<<S_LEN * NH / 8, 256>>>(kn, Cq);

    scan_kernel<<<128, 128>>>(kn, qn, vn, db, Cq, o);

    gnorm_kernel<<<S_LEN * NVH, 128>>>(o, gate, w_norm, og);

    gemm_tf32<<<g_o, blk, GDYN_SMEM>>>(og, wot, out, HID, VAL_DIM);
}

// round 10
// speedup vs baseline: 1.5660x; 1.4007x over previous
#include <cuda_runtime.h>
#include <cuda_fp16.h>
#include <math.h>
#include <stdint.h>

// ---------------- problem constants ----------------
#define S_LEN 4096
#define HID   2048
#define NH    8
#define NVH   16
#define DK    128
#define DV    128
#define KEY_DIM  (NH*DK)    // 1024
#define VAL_DIM  (NVH*DV)   // 2048
#define CONV  4
#define EPS_  1e-6f
#define SCALE_ 0.08838834764831845f   // 128^-0.5

// ---------------- workspace -------------------------------------------------
static constexpr size_t SZ_QPRE = (size_t)S_LEN * KEY_DIM;
static constexpr size_t SZ_VPRE = (size_t)S_LEN * VAL_DIM;
static constexpr size_t SZ_AB   = (size_t)S_LEN * NVH;
static constexpr size_t SZ_C    = (size_t)S_LEN * NH;
static constexpr size_t SZ_X    = (size_t)S_LEN * HID;
static constexpr size_t SZ_WQK  = (size_t)KEY_DIM * HID;
static constexpr size_t SZ_WV   = (size_t)VAL_DIM * HID;

static constexpr size_t OF_QPRE = 0;
static constexpr size_t OF_KPRE = OF_QPRE + SZ_QPRE;
static constexpr size_t OF_VPRE = OF_KPRE + SZ_QPRE;
static constexpr size_t OF_GATE = OF_VPRE + SZ_VPRE;
static constexpr size_t OF_QN   = OF_GATE + SZ_VPRE;
static constexpr size_t OF_KN   = OF_QN + SZ_QPRE;
static constexpr size_t OF_VN   = OF_KN + SZ_QPRE;
static constexpr size_t OF_DB   = OF_VN + SZ_VPRE;   // float2 per (t,h)
static constexpr size_t OF_CQ   = OF_DB + 2*SZ_AB;   // C[t][hk]
static constexpr size_t OF_O    = OF_CQ + SZ_C;
// fp16 buffers (element counts halved into float units)
static constexpr size_t OF_XH   = OF_O + SZ_VPRE;
static constexpr size_t OF_WQH  = OF_XH + SZ_X/2;
static constexpr size_t OF_WKH  = OF_WQH + SZ_WQK/2;
static constexpr size_t OF_WVH  = OF_WKH + SZ_WQK/2;
static constexpr size_t OF_WGH  = OF_WVH + SZ_WV/2;
static constexpr size_t OF_WOH  = OF_WGH + SZ_WV/2;
static constexpr size_t OF_OGH  = OF_WOH + SZ_WV/2;
static constexpr size_t WS_TOTAL = OF_OGH + SZ_VPRE/2;

__device__ float g_ws_gdn[WS_TOTAL];

// ---------------- cp.async helpers -----------------------------------------
__device__ __forceinline__ void cp16(void* s, const void* g) {
    asm volatile("cp.async.ca.shared.global [%0], [%1], 16;"
                 :: "r"((uint32_t)__cvta_generic_to_shared(s)), "l"(g));
}
__device__ __forceinline__ void cp8(void* s, const void* g) {
    asm volatile("cp.async.ca.shared.global [%0], [%1], 8;"
                 :: "r"((uint32_t)__cvta_generic_to_shared(s)), "l"(g));
}
__device__ __forceinline__ void cp4(void* s, const void* g) {
    asm volatile("cp.async.ca.shared.global [%0], [%1], 4;"
                 :: "r"((uint32_t)__cvta_generic_to_shared(s)), "l"(g));
}
__device__ __forceinline__ void cp_commit() {
    asm volatile("cp.async.commit_group;");
}

// ---------------- fp32 -> fp16 conversion ----------------------------------
__global__ __launch_bounds__(256) void cvt_h_kernel(
    const float* __restrict__ in, __half* __restrict__ out, int n)
{
    int i = (blockIdx.x * 256 + threadIdx.x) * 8;
    if (i >= n) return;
    float4 v0 = *(const float4*)(in + i);
    float4 v1 = *(const float4*)(in + i + 4);
    __half2 h[4];
    h[0] = __floats2half2_rn(v0.x, v0.y);
    h[1] = __floats2half2_rn(v0.z, v0.w);
    h[2] = __floats2half2_rn(v1.x, v1.y);
    h[3] = __floats2half2_rn(v1.z, v1.w);
    *(uint4*)(out + i) = *(uint4*)h;
}

// ================= fp16 tensor-core GEMM (4-stage cp.async) ================
// A[M,K], B[N,K] fp16 row-major; C fp32. M%128==0, N%128==0, K%16==0.
#define GBM 128
#define GBN 128
#define PADH 24                        // halves per row (48B: 16B-aligned, LDSM conflict-free)
#define STAGE_H (2 * GBM * PADH)       // 6144 halves per stage (A then B)
#define GDYN_SMEM (4 * STAGE_H * 2)    // 49152 bytes

__device__ __forceinline__ void mma_f16(float* c, const uint32_t* a, const uint32_t* b) {
    asm volatile(
        "mma.sync.aligned.m16n8k16.row.col.f32.f16.f16.f32 "
        "{%0,%1,%2,%3}, {%4,%5,%6,%7}, {%8,%9}, {%0,%1,%2,%3};"
        : "+f"(c[0]), "+f"(c[1]), "+f"(c[2]), "+f"(c[3])
        : "r"(a[0]), "r"(a[1]), "r"(a[2]), "r"(a[3]), "r"(b[0]), "r"(b[1]));
}

__device__ __forceinline__ void ldsm4(uint32_t* r, uint32_t addr) {
    asm volatile("ldmatrix.sync.aligned.m8n8.x4.shared.b16 {%0,%1,%2,%3}, [%4];"
                 : "=r"(r[0]), "=r"(r[1]), "=r"(r[2]), "=r"(r[3]) : "r"(addr));
}

__device__ __forceinline__ void gemm_core(
    const __half* __restrict__ A, const __half* __restrict__ B,
    float* __restrict__ C, int n0, int ldc, int K)
{
    extern __shared__ __half smh[];
    uint32_t sbase = (uint32_t)__cvta_generic_to_shared(smh);

    int tid = threadIdx.x;
    int warp = tid >> 5;
    int lane = tid & 31;
    int gid = lane >> 2;
    int tig = lane & 3;

    int m0 = blockIdx.y * GBM;
    int wm = (warp >> 2) * 64;
    int wn = (warp & 3) * 32;

    // producer: each thread cp16's 8 halves of one row for A and B
    int lrow = tid >> 1;
    int lk   = (tid & 1) * 8;
    const __half* Ag = A + (size_t)(m0 + lrow) * K + lk;
    const __half* Bg = B + (size_t)(n0 + lrow) * K + lk;
    int sA = lrow * PADH + lk;
    int sB = GBM * PADH + lrow * PADH + lk;

    // ldmatrix lane addressing (halves, relative to stage base)
    int arow = wm + (lane & 15);
    int akh  = (lane >> 4) * 8;
    int brow = wn + (lane & 7) + ((lane >> 4) << 3);
    int bkh  = ((lane >> 3) & 1) * 8;

    float acc[4][4][4];
#pragma unroll
    for (int i = 0; i < 4; i++)
#pragma unroll
        for (int j = 0; j < 4; j++)
#pragma unroll
            for (int r = 0; r < 4; r++) acc[i][j][r] = 0.f;

    int kIters = K / 16;

    // preload stages 0..2
#pragma unroll
    for (int s = 0; s < 3; s++) {
        __half* stg = smh + s * STAGE_H;
        cp16(stg + sA, Ag + (size_t)s * 16);
        cp16(stg + sB, Bg + (size_t)s * 16);
        cp_commit();
    }

    for (int it = 0; it < kIters; it++) {
        asm volatile("cp.async.wait_group 2;");
        __syncthreads();

        if (it + 3 < kIters) {
            __half* stg = smh + ((it + 3) & 3) * STAGE_H;
            cp16(stg + sA, Ag + (size_t)(it + 3) * 16);
            cp16(stg + sB, Bg + (size_t)(it + 3) * 16);
        }
        cp_commit();

        uint32_t stg = sbase + ((it & 3) * STAGE_H) * 2;
        uint32_t aaddr = stg + (uint32_t)(arow * PADH + akh) * 2;
        uint32_t baddr = stg + (uint32_t)(GBM * PADH + brow * PADH + bkh) * 2;

        uint32_t af[4][4], bfr[2][4];
#pragma unroll
        for (int mt = 0; mt < 4; mt++) ldsm4(af[mt], aaddr + mt * 16 * PADH * 2);
#pragma unroll
        for (int pt = 0; pt < 2; pt++) ldsm4(bfr[pt], baddr + pt * 16 * PADH * 2);

#pragma unroll
        for (int mt = 0; mt < 4; mt++)
#pragma unroll
            for (int nt = 0; nt < 4; nt++)
                mma_f16(acc[mt][nt], af[mt], &bfr[nt >> 1][(nt & 1) * 2]);
    }

#pragma unroll
    for (int mt = 0; mt < 4; mt++) {
#pragma unroll
        for (int nt = 0; nt < 4; nt++) {
            int m = m0 + wm + mt * 16 + gid;
            int n = n0 + wn + nt * 8 + tig * 2;
            *(float2*)&C[(size_t)m * ldc + n] = make_float2(acc[mt][nt][0], acc[mt][nt][1]);
            *(float2*)&C[(size_t)(m + 8) * ldc + n] = make_float2(acc[mt][nt][2], acc[mt][nt][3]);
        }
    }
}

// merged x-projection: blockIdx.x 0..7 Wq, 8..15 Wk, 16..31 Wv, 32..47 Wg
__global__ __launch_bounds__(256, 2) void gemm_x4(
    const __half* __restrict__ x,
    const __half* __restrict__ Wq, const __half* __restrict__ Wk,
    const __half* __restrict__ Wv, const __half* __restrict__ Wg,
    float* __restrict__ qpre, float* __restrict__ kpre,
    float* __restrict__ vpre, float* __restrict__ gate)
{
    int bx = blockIdx.x;
    const __half* B; float* C; int n0; int ldc;
    if (bx < 8)       { B = Wq; C = qpre; n0 = bx * 128;        ldc = KEY_DIM; }
    else if (bx < 16) { B = Wk; C = kpre; n0 = (bx - 8) * 128;  ldc = KEY_DIM; }
    else if (bx < 32) { B = Wv; C = vpre; n0 = (bx - 16) * 128; ldc = VAL_DIM; }
    else              { B = Wg; C = gate; n0 = (bx - 32) * 128; ldc = VAL_DIM; }
    gemm_core(x, B, C, n0, ldc, HID);
}

__global__ __launch_bounds__(256, 2) void gemm_h(
    const __half* __restrict__ A, const __half* __restrict__ B,
    float* __restrict__ C, int N, int K)
{
    gemm_core(A, B, C, blockIdx.x * GBN, N, K);
}

// ---------------- fused a/b projection + decay/beta -----------------------
__global__ __launch_bounds__(128) void gemv_ab(
    const float* __restrict__ x, const float* __restrict__ Wa,
    const float* __restrict__ Wb, const float* __restrict__ A_log,
    const float* __restrict__ dt_bias, float2* __restrict__ db)
{
    __shared__ float xs[8][260];
    __shared__ float was[16][260];
    __shared__ float wbs[16][260];

    int tid = threadIdx.x;
    int row = tid >> 4, n = tid & 15;
    int r0 = blockIdx.x * 8;

    float acc_a = 0.f, acc_b = 0.f;
    for (int kc = 0; kc < HID; kc += 256) {
        __syncthreads();
        int lr = tid >> 4, lo = (tid & 15) * 16;
#pragma unroll
        for (int j = 0; j < 16; j += 4)
            *(float4*)&xs[lr][lo + j] = *(const float4*)&x[(size_t)(r0 + lr) * HID + kc + lo + j];
        int wr = tid >> 3, wo = (tid & 7) * 32;
#pragma unroll
        for (int j = 0; j < 32; j += 4) {
            *(float4*)&was[wr][wo + j] = *(const float4*)&Wa[(size_t)wr * HID + kc + wo + j];
            *(float4*)&wbs[wr][wo + j] = *(const float4*)&Wb[(size_t)wr * HID + kc + wo + j];
        }
        __syncthreads();
#pragma unroll 8
        for (int j = 0; j < 256; j += 4) {
            float4 xv = *(float4*)&xs[row][j];
            float4 wa = *(float4*)&was[n][j];
            float4 wb = *(float4*)&wbs[n][j];
            acc_a += xv.x*wa.x + xv.y*wa.y + xv.z*wa.z + xv.w*wa.w;
            acc_b += xv.x*wb.x + xv.y*wb.y + xv.z*wb.z + xv.w*wb.w;
        }
    }
    float a = acc_a + dt_bias[n];
    float sp = (a > 20.f) ? a : log1pf(expf(a));
    float decay = expf(-expf(A_log[n]) * sp);
    float beta = 1.f / (1.f + expf(-acc_b));
    db[(size_t)(r0 + row) * NVH + n] = make_float2(decay, beta);
}

// ---------------- conv + silu + l2norm for q/k ----------------------------
__global__ __launch_bounds__(128) void convqk_kernel(
    const float* __restrict__ pre, const float* __restrict__ cw,
    float* __restrict__ out, float scale)
{
    int t = blockIdx.x >> 3;
    int h = blockIdx.x & 7;
    int c = threadIdx.x;
    int ch = h * DK + c;
    float y = 0.f;
#pragma unroll
    for (int j = 0; j < CONV; j++) {
        int tt = t - (CONV-1) + j;
        float xv = (tt >= 0) ? pre[(size_t)tt * KEY_DIM + ch] : 0.f;
        y = fmaf(xv, cw[ch*CONV + j], y);
    }
    y = y / (1.f + expf(-y));
    float ss = y * y;
#pragma unroll
    for (int off = 16; off; off >>= 1) ss += __shfl_xor_sync(0xffffffffu, ss, off);
    __shared__ float wss[4];
    if ((threadIdx.x & 31) == 0) wss[threadIdx.x >> 5] = ss;
    __syncthreads();
    float tot = wss[0] + wss[1] + wss[2] + wss[3];
    out[(size_t)t * KEY_DIM + ch] = y * rsqrtf(tot + EPS_) * scale;
}

// ---------------- conv + silu for v ---------------------------------------
__global__ __launch_bounds__(256) void convv_kernel(
    const float* __restrict__ pre, const float* __restrict__ cw,
    float* __restrict__ out)
{
    int idx = blockIdx.x * blockDim.x + threadIdx.x;
    int t = idx >> 11;
    int ch = idx & 2047;
    float y = 0.f;
#pragma unroll
    for (int j = 0; j < CONV; j++) {
        int tt = t - (CONV-1) + j;
        float xv = (tt >= 0) ? pre[(size_t)tt * VAL_DIM + ch] : 0.f;
        y = fmaf(xv, cw[ch*CONV + j], y);
    }
    out[idx] = y / (1.f + expf(-y));
}

// ---------------- C[t][hk] = k_{t+1} . k_t per key head --------------------
__global__ __launch_bounds__(256) void dotck_kernel(
    const float* __restrict__ k, float* __restrict__ Cq)
{
    int warp = threadIdx.x >> 5;
    int lane = threadIdx.x & 31;
    int idx = blockIdx.x * 8 + warp;       // t*NH + hk
    int t = idx >> 3, hk = idx & 7;
    float cv = 0.f;
    if (t + 1 < S_LEN) {
        const float* k0 = k + (size_t)t * KEY_DIM + hk * DK + lane * 4;
        const float* k1 = k0 + KEY_DIM;
        float4 a = *(const float4*)k0;
        float4 b = *(const float4*)k1;
        cv = a.x*b.x + a.y*b.y + a.z*b.z + a.w*b.w;
#pragma unroll
        for (int off = 16; off; off >>= 1) cv += __shfl_xor_sync(0xffffffffu, cv, off);
    }
    if (lane == 0) Cq[(size_t)t * NH + hk] = cv;
}

// ---------------- delta-rule scan v3 (scalarized serial chain) -------------
#define CH 16

__global__ __launch_bounds__(128) void scan_kernel(
    const float* __restrict__ k, const float* __restrict__ q,
    const float* __restrict__ v, const float2* __restrict__ db,
    const float* __restrict__ Cq, float* __restrict__ o)
{
    __shared__ float ks[2][CH + 1][DK];
    __shared__ float qs[2][CH][DK];
    __shared__ float vs[2][CH][16];
    __shared__ float2 dbs[2][CH];
    __shared__ float cs[2][CH];

    int h = blockIdx.x >> 3;
    int hk = h >> 1;
    int colbase = (blockIdx.x & 7) * 16;
    int tid = threadIdx.x;
    int w = tid >> 5, lane = tid & 31;
    int g = lane >> 3, s = lane & 7;
    int col = colbase + w * 4 + g;

    int lr = tid >> 3;
    int lo = (tid & 7) * 16;
    int vr = tid >> 2;

    const float* kbase = k + hk * DK;
    const float* qbase = q + hk * DK;
    const float* vbase = v + h * DV + colbase + (tid & 3) * 4;
    const float2* dbase = db + h;
    const float* cbase = Cq + hk;
    float* obase = o + h * DV + col;

    {
#pragma unroll
        for (int j = 0; j < 4; j++) {
            cp16(&ks[0][lr][lo + j*4], kbase + (size_t)lr * KEY_DIM + lo + j*4);
            cp16(&qs[0][lr][lo + j*4], qbase + (size_t)lr * KEY_DIM + lo + j*4);
        }
        if (tid < 8) {
#pragma unroll
            for (int j = 0; j < 4; j++)
                cp16(&ks[0][CH][tid*16 + j*4], kbase + (size_t)CH * KEY_DIM + tid*16 + j*4);
        }
        if (tid < 64) cp16(&vs[0][vr][(tid & 3) * 4], vbase + (size_t)vr * VAL_DIM);
        if (tid < CH) cp8(&dbs[0][tid], dbase + (size_t)tid * NVH);
        if (tid < CH) cp4(&cs[0][tid], cbase + (size_t)tid * NH);
        cp_commit();
    }

    float S[16];
#pragma unroll
    for (int i = 0; i < 16; i++) S[i] = 0.f;
    float P1 = 0.f;
    float kc[16];
    bool kc_init = false;

    int buf = 0;
    const int NCH = S_LEN / CH;
    for (int c = 0; c < NCH; c++) {
        if (c + 1 < NCH) {
            int t0 = (c + 1) * CH;
            int p = buf ^ 1;
#pragma unroll
            for (int j = 0; j < 4; j++) {
                cp16(&ks[p][lr][lo + j*4], kbase + (size_t)(t0 + lr) * KEY_DIM + lo + j*4);
                cp16(&qs[p][lr][lo + j*4], qbase + (size_t)(t0 + lr) * KEY_DIM + lo + j*4);
            }
            if (tid < 8) {
                int ovr = t0 + CH; if (ovr > S_LEN - 1) ovr = S_LEN - 1;
#pragma unroll
                for (int j = 0; j < 4; j++)
                    cp16(&ks[p][CH][tid*16 + j*4], kbase + (size_t)ovr * KEY_DIM + tid*16 + j*4);
            }
            if (tid < 64) cp16(&vs[p][vr][(tid & 3) * 4], vbase + (size_t)(t0 + vr) * VAL_DIM);
            if (tid < CH) cp8(&dbs[p][tid], dbase + (size_t)(t0 + tid) * NVH);
            if (tid < CH) cp4(&cs[p][tid], cbase + (size_t)(t0 + tid) * NH);
            cp_commit();
            asm volatile("cp.async.wait_group 1;");
        } else {
            asm volatile("cp.async.wait_group 0;");
        }
        __syncthreads();

        if (!kc_init) {
#pragma unroll
            for (int i = 0; i < 16; i += 4)
                *(float4*)&kc[i] = *(const float4*)&ks[0][0][s * 16 + i];
            kc_init = true;
        }

        int t0 = c * CH;
        float* ob = obase + (size_t)t0 * VAL_DIM;
#pragma unroll
        for (int tt = 0; tt < CH; tt++) {
            float kn[16], qc[16];
#pragma unroll
            for (int i = 0; i < 16; i += 4) {
                *(float4*)&kn[i] = *(const float4*)&ks[buf][tt + 1][s * 16 + i];
                *(float4*)&qc[i] = *(const float4*)&qs[buf][tt][s * 16 + i];
            }
            float vc = vs[buf][tt][w * 4 + g];
            float2 dc = dbs[buf][tt];
            float Ct = cs[buf][tt];

            float a0 = 0.f, a1 = 0.f, a2 = 0.f, a3 = 0.f;
#pragma unroll
            for (int i = 0; i < 16; i += 4) {
                a0 = fmaf(kn[i],   S[i],   a0);
                a1 = fmaf(kn[i+1], S[i+1], a1);
                a2 = fmaf(kn[i+2], S[i+2], a2);
                a3 = fmaf(kn[i+3], S[i+3], a3);
            }
            float A = (a0 + a1) + (a2 + a3);

            float delta = (vc - dc.x * P1) * dc.y;

            float b0 = 0.f, b1 = 0.f, b2 = 0.f, b3 = 0.f;
#pragma unroll
            for (int i = 0; i < 16; i += 4) {
                S[i]   = fmaf(S[i],   dc.x, kc[i]   * delta);
                S[i+1] = fmaf(S[i+1], dc.x, kc[i+1] * delta);
                S[i+2] = fmaf(S[i+2], dc.x, kc[i+2] * delta);
                S[i+3] = fmaf(S[i+3], dc.x, kc[i+3] * delta);
                b0 = fmaf(qc[i],   S[i],   b0);
                b1 = fmaf(qc[i+1], S[i+1], b1);
                b2 = fmaf(qc[i+2], S[i+2], b2);
                b3 = fmaf(qc[i+3], S[i+3], b3);
            }
            float ov = (b0 + b1) + (b2 + b3);

            A  += __shfl_xor_sync(0xffffffffu, A, 1);
            A  += __shfl_xor_sync(0xffffffffu, A, 2);
            A  += __shfl_xor_sync(0xffffffffu, A, 4);
            ov += __shfl_xor_sync(0xffffffffu, ov, 1);
            ov += __shfl_xor_sync(0xffffffffu, ov, 2);
            ov += __shfl_xor_sync(0xffffffffu, ov, 4);
            if (s == 0) ob[(size_t)tt * VAL_DIM] = ov;

            P1 = fmaf(dc.x, A, Ct * delta);
#pragma unroll
            for (int i = 0; i < 16; i++) kc[i] = kn[i];
        }
        __syncthreads();
        buf ^= 1;
    }
}

// ---------------- gated RMS norm (emits fp16 og) ---------------------------
__global__ __launch_bounds__(128) void gnorm_kernel(
    const float* __restrict__ o, const float* __restrict__ gate,
    const float* __restrict__ w_norm, __half* __restrict__ og)
{
    int t = blockIdx.x >> 4;
    int h = blockIdx.x & 15;
    int c = threadIdx.x;
    size_t idx = (size_t)t * VAL_DIM + h * DV + c;
    float gt = gate[idx];
    float y = o[idx] * (gt / (1.f + expf(-gt)));
    float ss = y * y;
#pragma unroll
    for (int off = 16; off; off >>= 1) ss += __shfl_xor_sync(0xffffffffu, ss, off);
    __shared__ float wss[4];
    if ((threadIdx.x & 31) == 0) wss[threadIdx.x >> 5] = ss;
    __syncthreads();
    float mean = (wss[0] + wss[1] + wss[2] + wss[3]) * (1.f / DV);
    og[idx] = __float2half_rn(y * rsqrtf(mean + EPS_) * w_norm[c]);
}

// ---------------- launch ---------------------------------------------------
extern "C" void kernel_launch(void* const* d_in, const int* in_sizes, int n_in,
                              void* d_out, int out_size)
{
    const float* x      = (const float*)d_in[0];
    const float* Wq     = (const float*)d_in[1];
    const float* Wk     = (const float*)d_in[2];
    const float* Wv     = (const float*)d_in[3];
    const float* Wa     = (const float*)d_in[4];
    const float* Wb     = (const float*)d_in[5];
    const float* Wg     = (const float*)d_in[6];
    const float* Wo     = (const float*)d_in[7];
    const float* conv_q = (const float*)d_in[8];
    const float* conv_k = (const float*)d_in[9];
    const float* conv_v = (const float*)d_in[10];
    const float* A_log  = (const float*)d_in[11];
    const float* dt_b   = (const float*)d_in[12];
    const float* w_norm = (const float*)d_in[13];

    void* wsp = nullptr;
    cudaGetSymbolAddress(&wsp, g_ws_gdn);
    float* ws = (float*)wsp;
    float* qpre = ws + OF_QPRE;
    float* kpre = ws + OF_KPRE;
    float* vpre = ws + OF_VPRE;
    float* gate = ws + OF_GATE;
    float* qn   = ws + OF_QN;
    float* kn   = ws + OF_KN;
    float* vn   = ws + OF_VN;
    float2* db  = (float2*)(ws + OF_DB);
    float* Cq   = ws + OF_CQ;
    float* o    = ws + OF_O;
    __half* xh  = (__half*)(ws + OF_XH);
    __half* wqh = (__half*)(ws + OF_WQH);
    __half* wkh = (__half*)(ws + OF_WKH);
    __half* wvh = (__half*)(ws + OF_WVH);
    __half* wgh = (__half*)(ws + OF_WGH);
    __half* woh = (__half*)(ws + OF_WOH);
    __half* ogh = (__half*)(ws + OF_OGH);
    float* out  = (float*)d_out;

    cudaFuncSetAttribute(gemm_x4, cudaFuncAttributeMaxDynamicSharedMemorySize, GDYN_SMEM);
    cudaFuncSetAttribute(gemm_h,  cudaFuncAttributeMaxDynamicSharedMemorySize, GDYN_SMEM);

    // fp16 pre-conversion (bandwidth-bound)
    cvt_h_kernel<<<(int)(SZ_X   / 2048), 256>>>(x,  xh,  (int)SZ_X);
    cvt_h_kernel<<<(int)(SZ_WQK / 2048), 256>>>(Wq, wqh, (int)SZ_WQK);
    cvt_h_kernel<<<(int)(SZ_WQK / 2048), 256>>>(Wk, wkh, (int)SZ_WQK);
    cvt_h_kernel<<<(int)(SZ_WV  / 2048), 256>>>(Wv, wvh, (int)SZ_WV);
    cvt_h_kernel<<<(int)(SZ_WV  / 2048), 256>>>(Wg, wgh, (int)SZ_WV);
    cvt_h_kernel<<<(int)(SZ_WV  / 2048), 256>>>(Wo, woh, (int)SZ_WV);

    dim3 blk(256);
    dim3 g_x4(48, S_LEN / GBM);              // merged Wq/Wk/Wv/Wg
    dim3 g_o (VAL_DIM / GBN, S_LEN / GBM);   // Wo: (16,32)

    gemm_x4<<<g_x4, blk, GDYN_SMEM>>>(xh, wqh, wkh, wvh, wgh, qpre, kpre, vpre, gate);
    gemv_ab<<<S_LEN / 8, 128>>>(x, Wa, Wb, A_log, dt_b, db);

    convqk_kernel<<<S_LEN * NH, 128>>>(qpre, conv_q, qn, SCALE_);
    convqk_kernel<<<S_LEN * NH, 128>>>(kpre, conv_k, kn, 1.f);
    convv_kernel<<<(S_LEN * VAL_DIM) / 256, 256>>>(vpre, conv_v, vn);
    dotck_kernel<<<S_LEN * NH / 8, 256>>>(kn, Cq);

    scan_kernel<<<128, 128>>>(kn, qn, vn, db, Cq, o);

    gnorm_kernel<<<S_LEN * NVH, 128>>>(o, gate, w_norm, ogh);

    gemm_h<<<g_o, blk, GDYN_SMEM>>>(ogh, woh, out, HID, VAL_DIM);
}

// round 11
// speedup vs baseline: 2.3317x; 1.4889x over previous
#include <cuda_runtime.h>
#include <cuda_fp16.h>
#include <math.h>
#include <stdint.h>

// ---------------- problem constants ----------------
#define S_LEN 4096
#define HID   2048
#define NH    8
#define NVH   16
#define DK    128
#define DV    128
#define KEY_DIM  (NH*DK)    // 1024
#define VAL_DIM  (NVH*DV)   // 2048
#define CONV  4
#define EPS_  1e-6f
#define SCALE_ 0.08838834764831845f   // 128^-0.5

// ---------------- workspace -------------------------------------------------
static constexpr size_t SZ_QPRE = (size_t)S_LEN * KEY_DIM;
static constexpr size_t SZ_VPRE = (size_t)S_LEN * VAL_DIM;
static constexpr size_t SZ_AB   = (size_t)S_LEN * NVH;
static constexpr size_t SZ_C    = (size_t)S_LEN * NH;
static constexpr size_t SZ_X    = (size_t)S_LEN * HID;
static constexpr size_t SZ_WQK  = (size_t)KEY_DIM * HID;
static constexpr size_t SZ_WV   = (size_t)VAL_DIM * HID;

static constexpr size_t OF_QPRE = 0;
static constexpr size_t OF_KPRE = OF_QPRE + SZ_QPRE;
static constexpr size_t OF_VPRE = OF_KPRE + SZ_QPRE;
static constexpr size_t OF_GATE = OF_VPRE + SZ_VPRE;
static constexpr size_t OF_QN   = OF_GATE + SZ_VPRE;
static constexpr size_t OF_KN   = OF_QN + SZ_QPRE;
static constexpr size_t OF_VN   = OF_KN + SZ_QPRE;
static constexpr size_t OF_DB   = OF_VN + SZ_VPRE;   // float2 per (t,h)
static constexpr size_t OF_CQ   = OF_DB + 2*SZ_AB;   // C[t][hk]
static constexpr size_t OF_O    = OF_CQ + SZ_C;
// fp16 buffers (element counts halved into float units)
static constexpr size_t OF_XH   = OF_O + SZ_VPRE;
static constexpr size_t OF_WQH  = OF_XH + SZ_X/2;
static constexpr size_t OF_WKH  = OF_WQH + SZ_WQK/2;
static constexpr size_t OF_WVH  = OF_WKH + SZ_WQK/2;
static constexpr size_t OF_WGH  = OF_WVH + SZ_WV/2;
static constexpr size_t OF_WOH  = OF_WGH + SZ_WV/2;
static constexpr size_t OF_OGH  = OF_WOH + SZ_WV/2;
static constexpr size_t WS_TOTAL = OF_OGH + SZ_VPRE/2;

__device__ float g_ws_gdn[WS_TOTAL];

// ---------------- cp.async helpers -----------------------------------------
__device__ __forceinline__ void cp16(void* s, const void* g) {
    asm volatile("cp.async.ca.shared.global [%0], [%1], 16;"
                 :: "r"((uint32_t)__cvta_generic_to_shared(s)), "l"(g));
}
__device__ __forceinline__ void cp8(void* s, const void* g) {
    asm volatile("cp.async.ca.shared.global [%0], [%1], 8;"
                 :: "r"((uint32_t)__cvta_generic_to_shared(s)), "l"(g));
}
__device__ __forceinline__ void cp4(void* s, const void* g) {
    asm volatile("cp.async.ca.shared.global [%0], [%1], 4;"
                 :: "r"((uint32_t)__cvta_generic_to_shared(s)), "l"(g));
}
__device__ __forceinline__ void cp_commit() {
    asm volatile("cp.async.commit_group;");
}

// ---------------- fp32 -> fp16 conversion ----------------------------------
__global__ __launch_bounds__(256) void cvt_h_kernel(
    const float* __restrict__ in, __half* __restrict__ out, int n)
{
    int i = (blockIdx.x * 256 + threadIdx.x) * 8;
    if (i >= n) return;
    float4 v0 = *(const float4*)(in + i);
    float4 v1 = *(const float4*)(in + i + 4);
    __half2 h[4];
    h[0] = __floats2half2_rn(v0.x, v0.y);
    h[1] = __floats2half2_rn(v0.z, v0.w);
    h[2] = __floats2half2_rn(v1.x, v1.y);
    h[3] = __floats2half2_rn(v1.z, v1.w);
    *(uint4*)(out + i) = *(uint4*)h;
}

// ================= fp16 tensor-core GEMM (4-stage cp.async) ================
#define GBM 128
#define GBN 128
#define PADH 24
#define STAGE_H (2 * GBM * PADH)
#define GDYN_SMEM (4 * STAGE_H * 2)    // 49152 bytes

__device__ __forceinline__ void mma_f16(float* c, const uint32_t* a, const uint32_t* b) {
    asm volatile(
        "mma.sync.aligned.m16n8k16.row.col.f32.f16.f16.f32 "
        "{%0,%1,%2,%3}, {%4,%5,%6,%7}, {%8,%9}, {%0,%1,%2,%3};"
        : "+f"(c[0]), "+f"(c[1]), "+f"(c[2]), "+f"(c[3])
        : "r"(a[0]), "r"(a[1]), "r"(a[2]), "r"(a[3]), "r"(b[0]), "r"(b[1]));
}

__device__ __forceinline__ void ldsm4(uint32_t* r, uint32_t addr) {
    asm volatile("ldmatrix.sync.aligned.m8n8.x4.shared.b16 {%0,%1,%2,%3}, [%4];"
                 : "=r"(r[0]), "=r"(r[1]), "=r"(r[2]), "=r"(r[3]) : "r"(addr));
}

__device__ __forceinline__ void gemm_core(
    const __half* __restrict__ A, const __half* __restrict__ B,
    float* __restrict__ C, int n0, int ldc, int K)
{
    extern __shared__ __half smh[];
    uint32_t sbase = (uint32_t)__cvta_generic_to_shared(smh);

    int tid = threadIdx.x;
    int warp = tid >> 5;
    int lane = tid & 31;
    int gid = lane >> 2;
    int tig = lane & 3;

    int m0 = blockIdx.y * GBM;
    int wm = (warp >> 2) * 64;
    int wn = (warp & 3) * 32;

    int lrow = tid >> 1;
    int lk   = (tid & 1) * 8;
    const __half* Ag = A + (size_t)(m0 + lrow) * K + lk;
    const __half* Bg = B + (size_t)(n0 + lrow) * K + lk;
    int sA = lrow * PADH + lk;
    int sB = GBM * PADH + lrow * PADH + lk;

    int arow = wm + (lane & 15);
    int akh  = (lane >> 4) * 8;
    int brow = wn + (lane & 7) + ((lane >> 4) << 3);
    int bkh  = ((lane >> 3) & 1) * 8;

    float acc[4][4][4];
#pragma unroll
    for (int i = 0; i < 4; i++)
#pragma unroll
        for (int j = 0; j < 4; j++)
#pragma unroll
            for (int r = 0; r < 4; r++) acc[i][j][r] = 0.f;

    int kIters = K / 16;

#pragma unroll
    for (int s = 0; s < 3; s++) {
        __half* stg = smh + s * STAGE_H;
        cp16(stg + sA, Ag + (size_t)s * 16);
        cp16(stg + sB, Bg + (size_t)s * 16);
        cp_commit();
    }

    for (int it = 0; it < kIters; it++) {
        asm volatile("cp.async.wait_group 2;");
        __syncthreads();

        if (it + 3 < kIters) {
            __half* stg = smh + ((it + 3) & 3) * STAGE_H;
            cp16(stg + sA, Ag + (size_t)(it + 3) * 16);
            cp16(stg + sB, Bg + (size_t)(it + 3) * 16);
        }
        cp_commit();

        uint32_t stg = sbase + ((it & 3) * STAGE_H) * 2;
        uint32_t aaddr = stg + (uint32_t)(arow * PADH + akh) * 2;
        uint32_t baddr = stg + (uint32_t)(GBM * PADH + brow * PADH + bkh) * 2;

        uint32_t af[4][4], bfr[2][4];
#pragma unroll
        for (int mt = 0; mt < 4; mt++) ldsm4(af[mt], aaddr + mt * 16 * PADH * 2);
#pragma unroll
        for (int pt = 0; pt < 2; pt++) ldsm4(bfr[pt], baddr + pt * 16 * PADH * 2);

#pragma unroll
        for (int mt = 0; mt < 4; mt++)
#pragma unroll
            for (int nt = 0; nt < 4; nt++)
                mma_f16(acc[mt][nt], af[mt], &bfr[nt >> 1][(nt & 1) * 2]);
    }

#pragma unroll
    for (int mt = 0; mt < 4; mt++) {
#pragma unroll
        for (int nt = 0; nt < 4; nt++) {
            int m = m0 + wm + mt * 16 + gid;
            int n = n0 + wn + nt * 8 + tig * 2;
            *(float2*)&C[(size_t)m * ldc + n] = make_float2(acc[mt][nt][0], acc[mt][nt][1]);
            *(float2*)&C[(size_t)(m + 8) * ldc + n] = make_float2(acc[mt][nt][2], acc[mt][nt][3]);
        }
    }
}

// merged x-projection: blockIdx.x 0..7 Wq, 8..15 Wk, 16..31 Wv, 32..47 Wg
__global__ __launch_bounds__(256, 2) void gemm_x4(
    const __half* __restrict__ x,
    const __half* __restrict__ Wq, const __half* __restrict__ Wk,
    const __half* __restrict__ Wv, const __half* __restrict__ Wg,
    float* __restrict__ qpre, float* __restrict__ kpre,
    float* __restrict__ vpre, float* __restrict__ gate)
{
    int bx = blockIdx.x;
    const __half* B; float* C; int n0; int ldc;
    if (bx < 8)       { B = Wq; C = qpre; n0 = bx * 128;        ldc = KEY_DIM; }
    else if (bx < 16) { B = Wk; C = kpre; n0 = (bx - 8) * 128;  ldc = KEY_DIM; }
    else if (bx < 32) { B = Wv; C = vpre; n0 = (bx - 16) * 128; ldc = VAL_DIM; }
    else              { B = Wg; C = gate; n0 = (bx - 32) * 128; ldc = VAL_DIM; }
    gemm_core(x, B, C, n0, ldc, HID);
}

__global__ __launch_bounds__(256, 2) void gemm_h(
    const __half* __restrict__ A, const __half* __restrict__ B,
    float* __restrict__ C, int N, int K)
{
    gemm_core(A, B, C, blockIdx.x * GBN, N, K);
}

// ---------------- fused a/b projection + decay/beta -----------------------
__global__ __launch_bounds__(128) void gemv_ab(
    const float* __restrict__ x, const float* __restrict__ Wa,
    const float* __restrict__ Wb, const float* __restrict__ A_log,
    const float* __restrict__ dt_bias, float2* __restrict__ db)
{
    __shared__ float xs[8][260];
    __shared__ float was[16][260];
    __shared__ float wbs[16][260];

    int tid = threadIdx.x;
    int row = tid >> 4, n = tid & 15;
    int r0 = blockIdx.x * 8;

    float acc_a = 0.f, acc_b = 0.f;
    for (int kc = 0; kc < HID; kc += 256) {
        __syncthreads();
        int lr = tid >> 4, lo = (tid & 15) * 16;
#pragma unroll
        for (int j = 0; j < 16; j += 4)
            *(float4*)&xs[lr][lo + j] = *(const float4*)&x[(size_t)(r0 + lr) * HID + kc + lo + j];
        int wr = tid >> 3, wo = (tid & 7) * 32;
#pragma unroll
        for (int j = 0; j < 32; j += 4) {
            *(float4*)&was[wr][wo + j] = *(const float4*)&Wa[(size_t)wr * HID + kc + wo + j];
            *(float4*)&wbs[wr][wo + j] = *(const float4*)&Wb[(size_t)wr * HID + kc + wo + j];
        }
        __syncthreads();
#pragma unroll 8
        for (int j = 0; j < 256; j += 4) {
            float4 xv = *(float4*)&xs[row][j];
            float4 wa = *(float4*)&was[n][j];
            float4 wb = *(float4*)&wbs[n][j];
            acc_a += xv.x*wa.x + xv.y*wa.y + xv.z*wa.z + xv.w*wa.w;
            acc_b += xv.x*wb.x + xv.y*wb.y + xv.z*wb.z + xv.w*wb.w;
        }
    }
    float a = acc_a + dt_bias[n];
    float sp = (a > 20.f) ? a : log1pf(expf(a));
    float decay = expf(-expf(A_log[n]) * sp);
    float beta = 1.f / (1.f + expf(-acc_b));
    db[(size_t)(r0 + row) * NVH + n] = make_float2(decay, beta);
}

// ---------------- conv + silu + l2norm for q/k ----------------------------
__global__ __launch_bounds__(128) void convqk_kernel(
    const float* __restrict__ pre, const float* __restrict__ cw,
    float* __restrict__ out, float scale)
{
    int t = blockIdx.x >> 3;
    int h = blockIdx.x & 7;
    int c = threadIdx.x;
    int ch = h * DK + c;
    float y = 0.f;
#pragma unroll
    for (int j = 0; j < CONV; j++) {
        int tt = t - (CONV-1) + j;
        float xv = (tt >= 0) ? pre[(size_t)tt * KEY_DIM + ch] : 0.f;
        y = fmaf(xv, cw[ch*CONV + j], y);
    }
    y = y / (1.f + expf(-y));
    float ss = y * y;
#pragma unroll
    for (int off = 16; off; off >>= 1) ss += __shfl_xor_sync(0xffffffffu, ss, off);
    __shared__ float wss[4];
    if ((threadIdx.x & 31) == 0) wss[threadIdx.x >> 5] = ss;
    __syncthreads();
    float tot = wss[0] + wss[1] + wss[2] + wss[3];
    out[(size_t)t * KEY_DIM + ch] = y * rsqrtf(tot + EPS_) * scale;
}

// ---------------- conv + silu for v ---------------------------------------
__global__ __launch_bounds__(256) void convv_kernel(
    const float* __restrict__ pre, const float* __restrict__ cw,
    float* __restrict__ out)
{
    int idx = blockIdx.x * blockDim.x + threadIdx.x;
    int t = idx >> 11;
    int ch = idx & 2047;
    float y = 0.f;
#pragma unroll
    for (int j = 0; j < CONV; j++) {
        int tt = t - (CONV-1) + j;
        float xv = (tt >= 0) ? pre[(size_t)tt * VAL_DIM + ch] : 0.f;
        y = fmaf(xv, cw[ch*CONV + j], y);
    }
    out[idx] = y / (1.f + expf(-y));
}

// ---------------- C[t][hk] = k_{t+1} . k_t per key head --------------------
__global__ __launch_bounds__(256) void dotck_kernel(
    const float* __restrict__ k, float* __restrict__ Cq)
{
    int warp = threadIdx.x >> 5;
    int lane = threadIdx.x & 31;
    int idx = blockIdx.x * 8 + warp;       // t*NH + hk
    int t = idx >> 3, hk = idx & 7;
    float cv = 0.f;
    if (t + 1 < S_LEN) {
        const float* k0 = k + (size_t)t * KEY_DIM + hk * DK + lane * 4;
        const float* k1 = k0 + KEY_DIM;
        float4 a = *(const float4*)k0;
        float4 b = *(const float4*)k1;
        cv = a.x*b.x + a.y*b.y + a.z*b.z + a.w*b.w;
#pragma unroll
        for (int off = 16; off; off >>= 1) cv += __shfl_xor_sync(0xffffffffu, cv, off);
    }
    if (lane == 0) Cq[(size_t)t * NH + hk] = cv;
}

// ---------------- delta-rule scan v5: conflict-free group-major k/q --------
// Group-major layout: k group g (floats g*16..g*16+15 of the head row) lives
// at ksw[g*KSTR + tt*16 .. +16). KSTR%8==4 => the 8 lanes' LDS.128 addresses
// hit 8 distinct bank groups -> 1 phase (was 4). Same for q with QSTR.
#define CH 16
#define KSTR 276   // 17 rows * 16 + 4 ; 276 % 8 == 4
#define QSTR 260   // 16 rows * 16 + 4 ; 260 % 8 == 4

__global__ __launch_bounds__(128) void scan_kernel(
    const float* __restrict__ k, const float* __restrict__ q,
    const float* __restrict__ v, const float2* __restrict__ db,
    const float* __restrict__ Cq, float* __restrict__ o)
{
    __shared__ float ksw[2][8 * KSTR];
    __shared__ float qsw[2][8 * QSTR];
    __shared__ float vs[2][CH][16];
    __shared__ float2 dbs[2][CH];
    __shared__ float cs[2][CH];

    int h = blockIdx.x >> 3;
    int hk = h >> 1;
    int colbase = (blockIdx.x & 7) * 16;
    int tid = threadIdx.x;
    int w = tid >> 5, lane = tid & 31;
    int g = lane >> 3, s = lane & 7;
    int col = colbase + w * 4 + g;

    // producer mapping: row plr (0..15), group pgp (0..7), 16 floats each
    int plr = tid >> 3;
    int pgp = tid & 7;
    int vr = tid >> 2;

    const float* kbase = k + hk * DK;
    const float* qbase = q + hk * DK;
    const float* vbase = v + h * DV + colbase + (tid & 3) * 4;
    const float2* dbase = db + h;
    const float* cbase = Cq + hk;
    float* obase = o + h * DV + col;

    // ---- issue chunk 0 ----
    {
        const float* krow = kbase + (size_t)plr * KEY_DIM + pgp * 16;
        const float* qrow = qbase + (size_t)plr * KEY_DIM + pgp * 16;
#pragma unroll
        for (int j = 0; j < 4; j++) {
            cp16(&ksw[0][pgp * KSTR + plr * 16 + j * 4], krow + j * 4);
            cp16(&qsw[0][pgp * QSTR + plr * 16 + j * 4], qrow + j * 4);
        }
        if (tid < 8) {
            const float* kov = kbase + (size_t)CH * KEY_DIM + tid * 16;
#pragma unroll
            for (int j = 0; j < 4; j++)
                cp16(&ksw[0][tid * KSTR + CH * 16 + j * 4], kov + j * 4);
        }
        if (tid < 64) cp16(&vs[0][vr][(tid & 3) * 4], vbase + (size_t)vr * VAL_DIM);
        if (tid < CH) cp8(&dbs[0][tid], dbase + (size_t)tid * NVH);
        if (tid < CH) cp4(&cs[0][tid], cbase + (size_t)tid * NH);
        cp_commit();
    }

    float S[16];
#pragma unroll
    for (int i = 0; i < 16; i++) S[i] = 0.f;
    float P1 = 0.f;
    float kc[16];
    bool kc_init = false;

    int buf = 0;
    const int NCH = S_LEN / CH;
    for (int c = 0; c < NCH; c++) {
        if (c + 1 < NCH) {
            int t0 = (c + 1) * CH;
            int p = buf ^ 1;
            const float* krow = kbase + (size_t)(t0 + plr) * KEY_DIM + pgp * 16;
            const float* qrow = qbase + (size_t)(t0 + plr) * KEY_DIM + pgp * 16;
#pragma unroll
            for (int j = 0; j < 4; j++) {
                cp16(&ksw[p][pgp * KSTR + plr * 16 + j * 4], krow + j * 4);
                cp16(&qsw[p][pgp * QSTR + plr * 16 + j * 4], qrow + j * 4);
            }
            if (tid < 8) {
                int ovr = t0 + CH; if (ovr > S_LEN - 1) ovr = S_LEN - 1;
                const float* kov = kbase + (size_t)ovr * KEY_DIM + tid * 16;
#pragma unroll
                for (int j = 0; j < 4; j++)
                    cp16(&ksw[p][tid * KSTR + CH * 16 + j * 4], kov + j * 4);
            }
            if (tid < 64) cp16(&vs[p][vr][(tid & 3) * 4], vbase + (size_t)(t0 + vr) * VAL_DIM);
            if (tid < CH) cp8(&dbs[p][tid], dbase + (size_t)(t0 + tid) * NVH);
            if (tid < CH) cp4(&cs[p][tid], cbase + (size_t)(t0 + tid) * NH);
            cp_commit();
            asm volatile("cp.async.wait_group 1;");
        } else {
            asm volatile("cp.async.wait_group 0;");
        }
        __syncthreads();

        if (!kc_init) {   // first chunk: load k_0 (group s, row 0)
#pragma unroll
            for (int i = 0; i < 16; i += 4)
                *(float4*)&kc[i] = *(const float4*)&ksw[0][s * KSTR + i];
            kc_init = true;
        }

        int t0 = c * CH;
        float* ob = obase + (size_t)t0 * VAL_DIM;
#pragma unroll
        for (int tt = 0; tt < CH; tt++) {
            float kn[16], qc[16];
#pragma unroll
            for (int i = 0; i < 16; i += 4) {
                *(float4*)&kn[i] = *(const float4*)&ksw[buf][s * KSTR + (tt + 1) * 16 + i];
                *(float4*)&qc[i] = *(const float4*)&qsw[buf][s * QSTR + tt * 16 + i];
            }
            float vc = vs[buf][tt][w * 4 + g];
            float2 dc = dbs[buf][tt];
            float Ct = cs[buf][tt];

            // A = k_{t+1} . S_{t-1}
            float a0 = 0.f, a1 = 0.f, a2 = 0.f, a3 = 0.f;
#pragma unroll
            for (int i = 0; i < 16; i += 4) {
                a0 = fmaf(kn[i],   S[i],   a0);
                a1 = fmaf(kn[i+1], S[i+1], a1);
                a2 = fmaf(kn[i+2], S[i+2], a2);
                a3 = fmaf(kn[i+3], S[i+3], a3);
            }
            float A = (a0 + a1) + (a2 + a3);

            float delta = (vc - dc.x * P1) * dc.y;

            float b0 = 0.f, b1 = 0.f, b2 = 0.f, b3 = 0.f;
#pragma unroll
            for (int i = 0; i < 16; i += 4) {
                S[i]   = fmaf(S[i],   dc.x, kc[i]   * delta);
                S[i+1] = fmaf(S[i+1], dc.x, kc[i+1] * delta);
                S[i+2] = fmaf(S[i+2], dc.x, kc[i+2] * delta);
                S[i+3] = fmaf(S[i+3], dc.x, kc[i+3] * delta);
                b0 = fmaf(qc[i],   S[i],   b0);
                b1 = fmaf(qc[i+1], S[i+1], b1);
                b2 = fmaf(qc[i+2], S[i+2], b2);
                b3 = fmaf(qc[i+3], S[i+3], b3);
            }
            float ov = (b0 + b1) + (b2 + b3);

            A  += __shfl_xor_sync(0xffffffffu, A, 1);
            A  += __shfl_xor_sync(0xffffffffu, A, 2);
            A  += __shfl_xor_sync(0xffffffffu, A, 4);
            ov += __shfl_xor_sync(0xffffffffu, ov, 1);
            ov += __shfl_xor_sync(0xffffffffu, ov, 2);
            ov += __shfl_xor_sync(0xffffffffu, ov, 4);
            if (s == 0) ob[(size_t)tt * VAL_DIM] = ov;

            P1 = fmaf(dc.x, A, Ct * delta);
#pragma unroll
            for (int i = 0; i < 16; i++) kc[i] = kn[i];
        }
        __syncthreads();
        buf ^= 1;
    }
}

// ---------------- gated RMS norm (emits fp16 og) ---------------------------
__global__ __launch_bounds__(128) void gnorm_kernel(
    const float* __restrict__ o, const float* __restrict__ gate,
    const float* __restrict__ w_norm, __half* __restrict__ og)
{
    int t = blockIdx.x >> 4;
    int h = blockIdx.x & 15;
    int c = threadIdx.x;
    size_t idx = (size_t)t * VAL_DIM + h * DV + c;
    float gt = gate[idx];
    float y = o[idx] * (gt / (1.f + expf(-gt)));
    float ss = y * y;
#pragma unroll
    for (int off = 16; off; off >>= 1) ss += __shfl_xor_sync(0xffffffffu, ss, off);
    __shared__ float wss[4];
    if ((threadIdx.x & 31) == 0) wss[threadIdx.x >> 5] = ss;
    __syncthreads();
    float mean = (wss[0] + wss[1] + wss[2] + wss[3]) * (1.f / DV);
    og[idx] = __float2half_rn(y * rsqrtf(mean + EPS_) * w_norm[c]);
}

// ---------------- launch ---------------------------------------------------
extern "C" void kernel_launch(void* const* d_in, const int* in_sizes, int n_in,
                              void* d_out, int out_size)
{
    const float* x      = (const float*)d_in[0];
    const float* Wq     = (const float*)d_in[1];
    const float* Wk     = (const float*)d_in[2];
    const float* Wv     = (const float*)d_in[3];
    const float* Wa     = (const float*)d_in[4];
    const float* Wb     = (const float*)d_in[5];
    const float* Wg     = (const float*)d_in[6];
    const float* Wo     = (const float*)d_in[7];
    const float* conv_q = (const float*)d_in[8];
    const float* conv_k = (const float*)d_in[9];
    const float* conv_v = (const float*)d_in[10];
    const float* A_log  = (const float*)d_in[11];
    const float* dt_b   = (const float*)d_in[12];
    const float* w_norm = (const float*)d_in[13];

    void* wsp = nullptr;
    cudaGetSymbolAddress(&wsp, g_ws_gdn);
    float* ws = (float*)wsp;
    float* qpre = ws + OF_QPRE;
    float* kpre = ws + OF_KPRE;
    float* vpre = ws + OF_VPRE;
    float* gate = ws + OF_GATE;
    float* qn   = ws + OF_QN;
    float* kn   = ws + OF_KN;
    float* vn   = ws + OF_VN;
    float2* db  = (float2*)(ws + OF_DB);
    float* Cq   = ws + OF_CQ;
    float* o    = ws + OF_O;
    __half* xh  = (__half*)(ws + OF_XH);
    __half* wqh = (__half*)(ws + OF_WQH);
    __half* wkh = (__half*)(ws + OF_WKH);
    __half* wvh = (__half*)(ws + OF_WVH);
    __half* wgh = (__half*)(ws + OF_WGH);
    __half* woh = (__half*)(ws + OF_WOH);
    __half* ogh = (__half*)(ws + OF_OGH);
    float* out  = (float*)d_out;

    cudaFuncSetAttribute(gemm_x4, cudaFuncAttributeMaxDynamicSharedMemorySize, GDYN_SMEM);
    cudaFuncSetAttribute(gemm_h,  cudaFuncAttributeMaxDynamicSharedMemorySize, GDYN_SMEM);

    cvt_h_kernel<<<(int)(SZ_X   / 2048), 256>>>(x,  xh,  (int)SZ_X);
    cvt_h_kernel<<<(int)(SZ_WQK / 2048), 256>>>(Wq, wqh, (int)SZ_WQK);
    cvt_h_kernel<<<(int)(SZ_WQK / 2048), 256>>>(Wk, wkh, (int)SZ_WQK);
    cvt_h_kernel<<<(int)(SZ_WV  / 2048), 256>>>(Wv, wvh, (int)SZ_WV);
    cvt_h_kernel<<<(int)(SZ_WV  / 2048), 256>>>(Wg, wgh, (int)SZ_WV);
    cvt_h_kernel<<<(int)(SZ_WV  / 2048), 256>>>(Wo, woh, (int)SZ_WV);

    dim3 blk(256);
    dim3 g_x4(48, S_LEN / GBM);
    dim3 g_o (VAL_DIM / GBN, S_LEN / GBM);

    gemm_x4<<<g_x4, blk, GDYN_SMEM>>>(xh, wqh, wkh, wvh, wgh, qpre, kpre, vpre, gate);
    gemv_ab<<<S_LEN / 8, 128>>>(x, Wa, Wb, A_log, dt_b, db);

    convqk_kernel<<<S_LEN * NH, 128>>>(qpre, conv_q, qn, SCALE_);
    convqk_kernel<<<S_LEN * NH, 128>>>(kpre, conv_k, kn, 1.f);
    convv_kernel<<<(S_LEN * VAL_DIM) / 256, 256>>>(vpre, conv_v, vn);
    dotck_kernel<<<S_LEN * NH / 8, 256>>>(kn, Cq);

    scan_kernel<<<128, 128>>>(kn, qn, vn, db, Cq, o);

    gnorm_kernel<<<S_LEN * NVH, 128>>>(o, gate, w_norm, ogh);

    gemm_h<<<g_o, blk, GDYN_SMEM>>>(ogh, woh, out, HID, VAL_DIM);
}

// round 12
// speedup vs baseline: 2.3490x; 1.0075x over previous
#include <cuda_runtime.h>
#include <cuda_fp16.h>
#include <math.h>
#include <stdint.h>

// ---------------- problem constants ----------------
#define S_LEN 4096
#define HID   2048
#define NH    8
#define NVH   16
#define DK    128
#define DV    128
#define KEY_DIM  (NH*DK)    // 1024
#define VAL_DIM  (NVH*DV)   // 2048
#define CONV  4
#define EPS_  1e-6f
#define SCALE_ 0.08838834764831845f   // 128^-0.5

// ---------------- workspace -------------------------------------------------
static constexpr size_t SZ_QPRE = (size_t)S_LEN * KEY_DIM;
static constexpr size_t SZ_VPRE = (size_t)S_LEN * VAL_DIM;
static constexpr size_t SZ_AB   = (size_t)S_LEN * NVH;
static constexpr size_t SZ_C    = (size_t)S_LEN * NH;
static constexpr size_t SZ_X    = (size_t)S_LEN * HID;
static constexpr size_t SZ_WQK  = (size_t)KEY_DIM * HID;
static constexpr size_t SZ_WV   = (size_t)VAL_DIM * HID;

static constexpr size_t OF_QPRE = 0;
static constexpr size_t OF_KPRE = OF_QPRE + SZ_QPRE;
static constexpr size_t OF_VPRE = OF_KPRE + SZ_QPRE;
static constexpr size_t OF_GATE = OF_VPRE + SZ_VPRE;
static constexpr size_t OF_QN   = OF_GATE + SZ_VPRE;
static constexpr size_t OF_KN   = OF_QN + SZ_QPRE;
static constexpr size_t OF_VN   = OF_KN + SZ_QPRE;
static constexpr size_t OF_DB   = OF_VN + SZ_VPRE;   // float2 per (t,h)
static constexpr size_t OF_CQ   = OF_DB + 2*SZ_AB;   // C[t][hk]
static constexpr size_t OF_O    = OF_CQ + SZ_C;
// fp16 buffers (element counts halved into float units)
static constexpr size_t OF_XH   = OF_O + SZ_VPRE;
static constexpr size_t OF_WQH  = OF_XH + SZ_X/2;
static constexpr size_t OF_WKH  = OF_WQH + SZ_WQK/2;
static constexpr size_t OF_WVH  = OF_WKH + SZ_WQK/2;
static constexpr size_t OF_WGH  = OF_WVH + SZ_WV/2;
static constexpr size_t OF_WOH  = OF_WGH + SZ_WV/2;
static constexpr size_t OF_OGH  = OF_WOH + SZ_WV/2;
static constexpr size_t WS_TOTAL = OF_OGH + SZ_VPRE/2;

__device__ float g_ws_gdn[WS_TOTAL];

// ---------------- cp.async helpers -----------------------------------------
__device__ __forceinline__ void cp16(void* s, const void* g) {
    asm volatile("cp.async.ca.shared.global [%0], [%1], 16;"
                 :: "r"((uint32_t)__cvta_generic_to_shared(s)), "l"(g));
}
__device__ __forceinline__ void cp8(void* s, const void* g) {
    asm volatile("cp.async.ca.shared.global [%0], [%1], 8;"
                 :: "r"((uint32_t)__cvta_generic_to_shared(s)), "l"(g));
}
__device__ __forceinline__ void cp4(void* s, const void* g) {
    asm volatile("cp.async.ca.shared.global [%0], [%1], 4;"
                 :: "r"((uint32_t)__cvta_generic_to_shared(s)), "l"(g));
}
__device__ __forceinline__ void cp_commit() {
    asm volatile("cp.async.commit_group;");
}

// ---------------- fp32 -> fp16 conversion ----------------------------------
__global__ __launch_bounds__(256) void cvt_h_kernel(
    const float* __restrict__ in, __half* __restrict__ out, int n)
{
    int i = (blockIdx.x * 256 + threadIdx.x) * 8;
    if (i >= n) return;
    float4 v0 = *(const float4*)(in + i);
    float4 v1 = *(const float4*)(in + i + 4);
    __half2 h[4];
    h[0] = __floats2half2_rn(v0.x, v0.y);
    h[1] = __floats2half2_rn(v0.z, v0.w);
    h[2] = __floats2half2_rn(v1.x, v1.y);
    h[3] = __floats2half2_rn(v1.z, v1.w);
    *(uint4*)(out + i) = *(uint4*)h;
}

// ================= fp16 tensor-core GEMM (k32 stages, 4-deep ring) =========
#define GBM 128
#define GBN 128
#define KC  32
#define PADH 40                        // halves per row (80B): LDSM conflict-free
#define STAGE_H (2 * GBM * PADH)       // 10240 halves per stage (A then B)
#define GDYN_SMEM (4 * STAGE_H * 2)    // 81920 bytes

__device__ __forceinline__ void mma_f16(float* c, const uint32_t* a, const uint32_t* b) {
    asm volatile(
        "mma.sync.aligned.m16n8k16.row.col.f32.f16.f16.f32 "
        "{%0,%1,%2,%3}, {%4,%5,%6,%7}, {%8,%9}, {%0,%1,%2,%3};"
        : "+f"(c[0]), "+f"(c[1]), "+f"(c[2]), "+f"(c[3])
        : "r"(a[0]), "r"(a[1]), "r"(a[2]), "r"(a[3]), "r"(b[0]), "r"(b[1]));
}

__device__ __forceinline__ void ldsm4(uint32_t* r, uint32_t addr) {
    asm volatile("ldmatrix.sync.aligned.m8n8.x4.shared.b16 {%0,%1,%2,%3}, [%4];"
                 : "=r"(r[0]), "=r"(r[1]), "=r"(r[2]), "=r"(r[3]) : "r"(addr));
}

__device__ __forceinline__ void gemm_core(
    const __half* __restrict__ A, const __half* __restrict__ B,
    float* __restrict__ C, int n0, int ldc, int K)
{
    extern __shared__ __half smh[];
    uint32_t sbase = (uint32_t)__cvta_generic_to_shared(smh);

    int tid = threadIdx.x;
    int warp = tid >> 5;
    int lane = tid & 31;
    int gid = lane >> 2;
    int tig = lane & 3;

    int m0 = blockIdx.y * GBM;
    int wm = (warp >> 2) * 64;
    int wn = (warp & 3) * 32;

    // producer: each thread cp16's 16 halves (2x cp16) of one row per matrix
    int lrow = tid >> 1;
    int lk   = (tid & 1) * 16;
    const __half* Ag = A + (size_t)(m0 + lrow) * K + lk;
    const __half* Bg = B + (size_t)(n0 + lrow) * K + lk;
    int sA = lrow * PADH + lk;
    int sB = GBM * PADH + lrow * PADH + lk;

    int arow = wm + (lane & 15);
    int akh  = (lane >> 4) * 8;
    int brow = wn + (lane & 7) + ((lane >> 4) << 3);
    int bkh  = ((lane >> 3) & 1) * 8;

    float acc[4][4][4];
#pragma unroll
    for (int i = 0; i < 4; i++)
#pragma unroll
        for (int j = 0; j < 4; j++)
#pragma unroll
            for (int r = 0; r < 4; r++) acc[i][j][r] = 0.f;

    int kIters = K / KC;

#pragma unroll
    for (int s = 0; s < 3; s++) {
        __half* stg = smh + s * STAGE_H;
        cp16(stg + sA,     Ag + (size_t)s * KC);
        cp16(stg + sA + 8, Ag + (size_t)s * KC + 8);
        cp16(stg + sB,     Bg + (size_t)s * KC);
        cp16(stg + sB + 8, Bg + (size_t)s * KC + 8);
        cp_commit();
    }

    for (int it = 0; it < kIters; it++) {
        asm volatile("cp.async.wait_group 2;");
        __syncthreads();

        if (it + 3 < kIters) {
            __half* stg = smh + ((it + 3) & 3) * STAGE_H;
            cp16(stg + sA,     Ag + (size_t)(it + 3) * KC);
            cp16(stg + sA + 8, Ag + (size_t)(it + 3) * KC + 8);
            cp16(stg + sB,     Bg + (size_t)(it + 3) * KC);
            cp16(stg + sB + 8, Bg + (size_t)(it + 3) * KC + 8);
        }
        cp_commit();

        uint32_t stg = sbase + ((it & 3) * STAGE_H) * 2;

#pragma unroll
        for (int sub = 0; sub < 2; sub++) {
            int cb = sub * 16;
            uint32_t aaddr = stg + (uint32_t)(arow * PADH + cb + akh) * 2;
            uint32_t baddr = stg + (uint32_t)(GBM * PADH + brow * PADH + cb + bkh) * 2;

            uint32_t af[4][4], bfr[2][4];
#pragma unroll
            for (int mt = 0; mt < 4; mt++) ldsm4(af[mt], aaddr + mt * 16 * PADH * 2);
#pragma unroll
            for (int pt = 0; pt < 2; pt++) ldsm4(bfr[pt], baddr + pt * 16 * PADH * 2);

#pragma unroll
            for (int mt = 0; mt < 4; mt++)
#pragma unroll
                for (int nt = 0; nt < 4; nt++)
                    mma_f16(acc[mt][nt], af[mt], &bfr[nt >> 1][(nt & 1) * 2]);
        }
    }

#pragma unroll
    for (int mt = 0; mt < 4; mt++) {
#pragma unroll
        for (int nt = 0; nt < 4; nt++) {
            int m = m0 + wm + mt * 16 + gid;
            int n = n0 + wn + nt * 8 + tig * 2;
            *(float2*)&C[(size_t)m * ldc + n] = make_float2(acc[mt][nt][0], acc[mt][nt][1]);
            *(float2*)&C[(size_t)(m + 8) * ldc + n] = make_float2(acc[mt][nt][2], acc[mt][nt][3]);
        }
    }
}

// merged x-projection: blockIdx.x 0..7 Wq, 8..15 Wk, 16..31 Wv, 32..47 Wg
__global__ __launch_bounds__(256, 2) void gemm_x4(
    const __half* __restrict__ x,
    const __half* __restrict__ Wq, const __half* __restrict__ Wk,
    const __half* __restrict__ Wv, const __half* __restrict__ Wg,
    float* __restrict__ qpre, float* __restrict__ kpre,
    float* __restrict__ vpre, float* __restrict__ gate)
{
    int bx = blockIdx.x;
    const __half* B; float* C; int n0; int ldc;
    if (bx < 8)       { B = Wq; C = qpre; n0 = bx * 128;        ldc = KEY_DIM; }
    else if (bx < 16) { B = Wk; C = kpre; n0 = (bx - 8) * 128;  ldc = KEY_DIM; }
    else if (bx < 32) { B = Wv; C = vpre; n0 = (bx - 16) * 128; ldc = VAL_DIM; }
    else              { B = Wg; C = gate; n0 = (bx - 32) * 128; ldc = VAL_DIM; }
    gemm_core(x, B, C, n0, ldc, HID);
}

__global__ __launch_bounds__(256, 2) void gemm_h(
    const __half* __restrict__ A, const __half* __restrict__ B,
    float* __restrict__ C, int N, int K)
{
    gemm_core(A, B, C, blockIdx.x * GBN, N, K);
}

// ---------------- fused a/b projection + decay/beta -----------------------
__global__ __launch_bounds__(128) void gemv_ab(
    const float* __restrict__ x, const float* __restrict__ Wa,
    const float* __restrict__ Wb, const float* __restrict__ A_log,
    const float* __restrict__ dt_bias, float2* __restrict__ db)
{
    __shared__ float xs[8][260];
    __shared__ float was[16][260];
    __shared__ float wbs[16][260];

    int tid = threadIdx.x;
    int row = tid >> 4, n = tid & 15;
    int r0 = blockIdx.x * 8;

    float acc_a = 0.f, acc_b = 0.f;
    for (int kc = 0; kc < HID; kc += 256) {
        __syncthreads();
        int lr = tid >> 4, lo = (tid & 15) * 16;
#pragma unroll
        for (int j = 0; j < 16; j += 4)
            *(float4*)&xs[lr][lo + j] = *(const float4*)&x[(size_t)(r0 + lr) * HID + kc + lo + j];
        int wr = tid >> 3, wo = (tid & 7) * 32;
#pragma unroll
        for (int j = 0; j < 32; j += 4) {
            *(float4*)&was[wr][wo + j] = *(const float4*)&Wa[(size_t)wr * HID + kc + wo + j];
            *(float4*)&wbs[wr][wo + j] = *(const float4*)&Wb[(size_t)wr * HID + kc + wo + j];
        }
        __syncthreads();
#pragma unroll 8
        for (int j = 0; j < 256; j += 4) {
            float4 xv = *(float4*)&xs[row][j];
            float4 wa = *(float4*)&was[n][j];
            float4 wb = *(float4*)&wbs[n][j];
            acc_a += xv.x*wa.x + xv.y*wa.y + xv.z*wa.z + xv.w*wa.w;
            acc_b += xv.x*wb.x + xv.y*wb.y + xv.z*wb.z + xv.w*wb.w;
        }
    }
    float a = acc_a + dt_bias[n];
    float sp = (a > 20.f) ? a : log1pf(expf(a));
    float decay = expf(-expf(A_log[n]) * sp);
    float beta = 1.f / (1.f + expf(-acc_b));
    db[(size_t)(r0 + row) * NVH + n] = make_float2(decay, beta);
}

// ---------------- conv + silu + l2norm for q/k ----------------------------
__global__ __launch_bounds__(128) void convqk_kernel(
    const float* __restrict__ pre, const float* __restrict__ cw,
    float* __restrict__ out, float scale)
{
    int t = blockIdx.x >> 3;
    int h = blockIdx.x & 7;
    int c = threadIdx.x;
    int ch = h * DK + c;
    float y = 0.f;
#pragma unroll
    for (int j = 0; j < CONV; j++) {
        int tt = t - (CONV-1) + j;
        float xv = (tt >= 0) ? pre[(size_t)tt * KEY_DIM + ch] : 0.f;
        y = fmaf(xv, cw[ch*CONV + j], y);
    }
    y = y / (1.f + expf(-y));
    float ss = y * y;
#pragma unroll
    for (int off = 16; off; off >>= 1) ss += __shfl_xor_sync(0xffffffffu, ss, off);
    __shared__ float wss[4];
    if ((threadIdx.x & 31) == 0) wss[threadIdx.x >> 5] = ss;
    __syncthreads();
    float tot = wss[0] + wss[1] + wss[2] + wss[3];
    out[(size_t)t * KEY_DIM + ch] = y * rsqrtf(tot + EPS_) * scale;
}

// ---------------- conv + silu for v ---------------------------------------
__global__ __launch_bounds__(256) void convv_kernel(
    const float* __restrict__ pre, const float* __restrict__ cw,
    float* __restrict__ out)
{
    int idx = blockIdx.x * blockDim.x + threadIdx.x;
    int t = idx >> 11;
    int ch = idx & 2047;
    float y = 0.f;
#pragma unroll
    for (int j = 0; j < CONV; j++) {
        int tt = t - (CONV-1) + j;
        float xv = (tt >= 0) ? pre[(size_t)tt * VAL_DIM + ch] : 0.f;
        y = fmaf(xv, cw[ch*CONV + j], y);
    }
    out[idx] = y / (1.f + expf(-y));
}

// ---------------- C[t][hk] = k_{t+1} . k_t per key head --------------------
__global__ __launch_bounds__(256) void dotck_kernel(
    const float* __restrict__ k, float* __restrict__ Cq)
{
    int warp = threadIdx.x >> 5;
    int lane = threadIdx.x & 31;
    int idx = blockIdx.x * 8 + warp;       // t*NH + hk
    int t = idx >> 3, hk = idx & 7;
    float cv = 0.f;
    if (t + 1 < S_LEN) {
        const float* k0 = k + (size_t)t * KEY_DIM + hk * DK + lane * 4;
        const float* k1 = k0 + KEY_DIM;
        float4 a = *(const float4*)k0;
        float4 b = *(const float4*)k1;
        cv = a.x*b.x + a.y*b.y + a.z*b.z + a.w*b.w;
#pragma unroll
        for (int off = 16; off; off >>= 1) cv += __shfl_xor_sync(0xffffffffu, cv, off);
    }
    if (lane == 0) Cq[(size_t)t * NH + hk] = cv;
}

// ---------------- delta-rule scan v5: conflict-free group-major k/q --------
#define CH 16
#define KSTR 276   // 17 rows * 16 + 4 ; 276 % 8 == 4
#define QSTR 260   // 16 rows * 16 + 4 ; 260 % 8 == 4

__global__ __launch_bounds__(128) void scan_kernel(
    const float* __restrict__ k, const float* __restrict__ q,
    const float* __restrict__ v, const float2* __restrict__ db,
    const float* __restrict__ Cq, float* __restrict__ o)
{
    __shared__ float ksw[2][8 * KSTR];
    __shared__ float qsw[2][8 * QSTR];
    __shared__ float vs[2][CH][16];
    __shared__ float2 dbs[2][CH];
    __shared__ float cs[2][CH];

    int h = blockIdx.x >> 3;
    int hk = h >> 1;
    int colbase = (blockIdx.x & 7) * 16;
    int tid = threadIdx.x;
    int w = tid >> 5, lane = tid & 31;
    int g = lane >> 3, s = lane & 7;
    int col = colbase + w * 4 + g;

    int plr = tid >> 3;
    int pgp = tid & 7;
    int vr = tid >> 2;

    const float* kbase = k + hk * DK;
    const float* qbase = q + hk * DK;
    const float* vbase = v + h * DV + colbase + (tid & 3) * 4;
    const float2* dbase = db + h;
    const float* cbase = Cq + hk;
    float* obase = o + h * DV + col;

    {
        const float* krow = kbase + (size_t)plr * KEY_DIM + pgp * 16;
        const float* qrow = qbase + (size_t)plr * KEY_DIM + pgp * 16;
#pragma unroll
        for (int j = 0; j < 4; j++) {
            cp16(&ksw[0][pgp * KSTR + plr * 16 + j * 4], krow + j * 4);
            cp16(&qsw[0][pgp * QSTR + plr * 16 + j * 4], qrow + j * 4);
        }
        if (tid < 8) {
            const float* kov = kbase + (size_t)CH * KEY_DIM + tid * 16;
#pragma unroll
            for (int j = 0; j < 4; j++)
                cp16(&ksw[0][tid * KSTR + CH * 16 + j * 4], kov + j * 4);
        }
        if (tid < 64) cp16(&vs[0][vr][(tid & 3) * 4], vbase + (size_t)vr * VAL_DIM);
        if (tid < CH) cp8(&dbs[0][tid], dbase + (size_t)tid * NVH);
        if (tid < CH) cp4(&cs[0][tid], cbase + (size_t)tid * NH);
        cp_commit();
    }

    float S[16];
#pragma unroll
    for (int i = 0; i < 16; i++) S[i] = 0.f;
    float P1 = 0.f;
    float kc[16];
    bool kc_init = false;

    int buf = 0;
    const int NCH = S_LEN / CH;
    for (int c = 0; c < NCH; c++) {
        if (c + 1 < NCH) {
            int t0 = (c + 1) * CH;
            int p = buf ^ 1;
            const float* krow = kbase + (size_t)(t0 + plr) * KEY_DIM + pgp * 16;
            const float* qrow = qbase + (size_t)(t0 + plr) * KEY_DIM + pgp * 16;
#pragma unroll
            for (int j = 0; j < 4; j++) {
                cp16(&ksw[p][pgp * KSTR + plr * 16 + j * 4], krow + j * 4);
                cp16(&qsw[p][pgp * QSTR + plr * 16 + j * 4], qrow + j * 4);
            }
            if (tid < 8) {
                int ovr = t0 + CH; if (ovr > S_LEN - 1) ovr = S_LEN - 1;
                const float* kov = kbase + (size_t)ovr * KEY_DIM + tid * 16;
#pragma unroll
                for (int j = 0; j < 4; j++)
                    cp16(&ksw[p][tid * KSTR + CH * 16 + j * 4], kov + j * 4);
            }
            if (tid < 64) cp16(&vs[p][vr][(tid & 3) * 4], vbase + (size_t)(t0 + vr) * VAL_DIM);
            if (tid < CH) cp8(&dbs[p][tid], dbase + (size_t)(t0 + tid) * NVH);
            if (tid < CH) cp4(&cs[p][tid], cbase + (size_t)(t0 + tid) * NH);
            cp_commit();
            asm volatile("cp.async.wait_group 1;");
        } else {
            asm volatile("cp.async.wait_group 0;");
        }
        __syncthreads();

        if (!kc_init) {
#pragma unroll
            for (int i = 0; i < 16; i += 4)
                *(float4*)&kc[i] = *(const float4*)&ksw[0][s * KSTR + i];
            kc_init = true;
        }

        int t0 = c * CH;
        float* ob = obase + (size_t)t0 * VAL_DIM;
#pragma unroll
        for (int tt = 0; tt < CH; tt++) {
            float kn[16], qc[16];
#pragma unroll
            for (int i = 0; i < 16; i += 4) {
                *(float4*)&kn[i] = *(const float4*)&ksw[buf][s * KSTR + (tt + 1) * 16 + i];
                *(float4*)&qc[i] = *(const float4*)&qsw[buf][s * QSTR + tt * 16 + i];
            }
            float vc = vs[buf][tt][w * 4 + g];
            float2 dc = dbs[buf][tt];
            float Ct = cs[buf][tt];

            float a0 = 0.f, a1 = 0.f, a2 = 0.f, a3 = 0.f;
#pragma unroll
            for (int i = 0; i < 16; i += 4) {
                a0 = fmaf(kn[i],   S[i],   a0);
                a1 = fmaf(kn[i+1], S[i+1], a1);
                a2 = fmaf(kn[i+2], S[i+2], a2);
                a3 = fmaf(kn[i+3], S[i+3], a3);
            }
            float A = (a0 + a1) + (a2 + a3);

            float delta = (vc - dc.x * P1) * dc.y;

            float b0 = 0.f, b1 = 0.f, b2 = 0.f, b3 = 0.f;
#pragma unroll
            for (int i = 0; i < 16; i += 4) {
                S[i]   = fmaf(S[i],   dc.x, kc[i]   * delta);
                S[i+1] = fmaf(S[i+1], dc.x, kc[i+1] * delta);
                S[i+2] = fmaf(S[i+2], dc.x, kc[i+2] * delta);
                S[i+3] = fmaf(S[i+3], dc.x, kc[i+3] * delta);
                b0 = fmaf(qc[i],   S[i],   b0);
                b1 = fmaf(qc[i+1], S[i+1], b1);
                b2 = fmaf(qc[i+2], S[i+2], b2);
                b3 = fmaf(qc[i+3], S[i+3], b3);
            }
            float ov = (b0 + b1) + (b2 + b3);

            A  += __shfl_xor_sync(0xffffffffu, A, 1);
            A  += __shfl_xor_sync(0xffffffffu, A, 2);
            A  += __shfl_xor_sync(0xffffffffu, A, 4);
            ov += __shfl_xor_sync(0xffffffffu, ov, 1);
            ov += __shfl_xor_sync(0xffffffffu, ov, 2);
            ov += __shfl_xor_sync(0xffffffffu, ov, 4);
            if (s == 0) ob[(size_t)tt * VAL_DIM] = ov;

            P1 = fmaf(dc.x, A, Ct * delta);
#pragma unroll
            for (int i = 0; i < 16; i++) kc[i] = kn[i];
        }
        __syncthreads();
        buf ^= 1;
    }
}

// ---------------- gated RMS norm (emits fp16 og) ---------------------------
__global__ __launch_bounds__(128) void gnorm_kernel(
    const float* __restrict__ o, const float* __restrict__ gate,
    const float* __restrict__ w_norm, __half* __restrict__ og)
{
    int t = blockIdx.x >> 4;
    int h = blockIdx.x & 15;
    int c = threadIdx.x;
    size_t idx = (size_t)t * VAL_DIM + h * DV + c;
    float gt = gate[idx];
    float y = o[idx] * (gt / (1.f + expf(-gt)));
    float ss = y * y;
#pragma unroll
    for (int off = 16; off; off >>= 1) ss += __shfl_xor_sync(0xffffffffu, ss, off);
    __shared__ float wss[4];
    if ((threadIdx.x & 31) == 0) wss[threadIdx.x >> 5] = ss;
    __syncthreads();
    float mean = (wss[0] + wss[1] + wss[2] + wss[3]) * (1.f / DV);
    og[idx] = __float2half_rn(y * rsqrtf(mean + EPS_) * w_norm[c]);
}

// ---------------- launch ---------------------------------------------------
extern "C" void kernel_launch(void* const* d_in, const int* in_sizes, int n_in,
                              void* d_out, int out_size)
{
    const float* x      = (const float*)d_in[0];
    const float* Wq     = (const float*)d_in[1];
    const float* Wk     = (const float*)d_in[2];
    const float* Wv     = (const float*)d_in[3];
    const float* Wa     = (const float*)d_in[4];
    const float* Wb     = (const float*)d_in[5];
    const float* Wg     = (const float*)d_in[6];
    const float* Wo     = (const float*)d_in[7];
    const float* conv_q = (const float*)d_in[8];
    const float* conv_k = (const float*)d_in[9];
    const float* conv_v = (const float*)d_in[10];
    const float* A_log  = (const float*)d_in[11];
    const float* dt_b   = (const float*)d_in[12];
    const float* w_norm = (const float*)d_in[13];

    void* wsp = nullptr;
    cudaGetSymbolAddress(&wsp, g_ws_gdn);
    float* ws = (float*)wsp;
    float* qpre = ws + OF_QPRE;
    float* kpre = ws + OF_KPRE;
    float* vpre = ws + OF_VPRE;
    float* gate = ws + OF_GATE;
    float* qn   = ws + OF_QN;
    float* kn   = ws + OF_KN;
    float* vn   = ws + OF_VN;
    float2* db  = (float2*)(ws + OF_DB);
    float* Cq   = ws + OF_CQ;
    float* o    = ws + OF_O;
    __half* xh  = (__half*)(ws + OF_XH);
    __half* wqh = (__half*)(ws + OF_WQH);
    __half* wkh = (__half*)(ws + OF_WKH);
    __half* wvh = (__half*)(ws + OF_WVH);
    __half* wgh = (__half*)(ws + OF_WGH);
    __half* woh = (__half*)(ws + OF_WOH);
    __half* ogh = (__half*)(ws + OF_OGH);
    float* out  = (float*)d_out;

    cudaFuncSetAttribute(gemm_x4, cudaFuncAttributeMaxDynamicSharedMemorySize, GDYN_SMEM);
    cudaFuncSetAttribute(gemm_h,  cudaFuncAttributeMaxDynamicSharedMemorySize, GDYN_SMEM);

    cvt_h_kernel<<<(int)(SZ_X   / 2048), 256>>>(x,  xh,  (int)SZ_X);
    cvt_h_kernel<<<(int)(SZ_WQK / 2048), 256>>>(Wq, wqh, (int)SZ_WQK);
    cvt_h_kernel<<<(int)(SZ_WQK / 2048), 256>>>(Wk, wkh, (int)SZ_WQK);
    cvt_h_kernel<<<(int)(SZ_WV  / 2048), 256>>>(Wv, wvh, (int)SZ_WV);
    cvt_h_kernel<<<(int)(SZ_WV  / 2048), 256>>>(Wg, wgh, (int)SZ_WV);
    cvt_h_kernel<<<(int)(SZ_WV  / 2048), 256>>>(Wo, woh, (int)SZ_WV);

    dim3 blk(256);
    dim3 g_x4(48, S_LEN / GBM);
    dim3 g_o (VAL_DIM / GBN, S_LEN / GBM);

    gemm_x4<<<g_x4, blk, GDYN_SMEM>>>(xh, wqh, wkh, wvh, wgh, qpre, kpre, vpre, gate);
    gemv_ab<<<S_LEN / 8, 128>>>(x, Wa, Wb, A_log, dt_b, db);

    convqk_kernel<<<S_LEN * NH, 128>>>(qpre, conv_q, qn, SCALE_);
    convqk_kernel<<<S_LEN * NH, 128>>>(kpre, conv_k, kn, 1.f);
    convv_kernel<<<(S_LEN * VAL_DIM) / 256, 256>>>(vpre, conv_v, vn);
    dotck_kernel<<<S_LEN * NH / 8, 256>>>(kn, Cq);

    scan_kernel<<<128, 128>>>(kn, qn, vn, db, Cq, o);

    gnorm_kernel<<<S_LEN * NVH, 128>>>(o, gate, w_norm, ogh);

    gemm_h<<<g_o, blk, GDYN_SMEM>>>(ogh, woh, out, HID, VAL_DIM);
}